// round 6
// baseline (speedup 1.0000x reference)
#include <cuda_runtime.h>
#include <math.h>
#include <stdint.h>

#define BB 4
#define TT 4096
#define CC 512
#define HD 64

#define BM 128           // q-tile rows per flash CTA
#define BN 64            // kv-tile rows
#define SPLIT 16         // max KV tiles per work item
#define QB_PER_B 32      // TT / BM
#define NITEMS_PER_B 80
#define NITEMS (BB * NITEMS_PER_B)   // 320
#define PAD 68           // flash smem row stride

// q/k/v stored as tf32 bit patterns (q pre-scaled by C^-0.5 * log2e)
__device__ uint32_t g_q[BB * TT * HD];
__device__ uint32_t g_k[BB * TT * HD];
__device__ uint32_t g_v[BB * TT * HD];

// split-KV partials
__device__ float g_pacc[BB * QB_PER_B * 4 * BM * HD];
__device__ float g_pm[BB * QB_PER_B * 4 * BM];
__device__ float g_pl[BB * QB_PER_B * 4 * BM];

__device__ __forceinline__ uint32_t f2tf(float f) {
    uint32_t u;
    asm("cvt.rna.tf32.f32 %0, %1;" : "=r"(u) : "f"(f));
    return u;
}

__device__ __forceinline__ void mma_tf32(float& d0, float& d1, float& d2, float& d3,
                                         uint32_t a0, uint32_t a1, uint32_t a2, uint32_t a3,
                                         uint32_t b0, uint32_t b1) {
    asm volatile(
        "mma.sync.aligned.m16n8k8.row.col.f32.tf32.tf32.f32 "
        "{%0,%1,%2,%3}, {%4,%5,%6,%7}, {%8,%9}, {%0,%1,%2,%3};"
        : "+f"(d0), "+f"(d1), "+f"(d2), "+f"(d3)
        : "r"(a0), "r"(a1), "r"(a2), "r"(a3), "r"(b0), "r"(b1));
}

// split v into tf32 hi + tf32 lo (3xTF32 compensation)
__device__ __forceinline__ void tf_split(float v, uint32_t& hi, uint32_t& lo) {
    hi = f2tf(v);
    float hif = __uint_as_float(hi);
    lo = f2tf(v - hif);
}

// ---------------------------------------------------------------------------
// Fused projection GEMM (3xTF32, near-fp32 accurate): [16384x512]@[512x192]
// Grid 128 CTAs x 512 threads (16 warps). Warp w: rows 32*(w&3), cols 48*(w>>2).
// K-chunks of 64, single-buffered hi/lo smem (172 KB).
// ---------------------------------------------------------------------------
#define PX 68
#define PW 200
#define XS_SZ (128 * PX)
#define WS_SZ (64 * PW)

__global__ __launch_bounds__(512, 1) void proj_kernel(const float* __restrict__ x,
                                                      const float* __restrict__ Wk,
                                                      const float* __restrict__ Wq,
                                                      const float* __restrict__ Wv) {
    extern __shared__ uint32_t psm[];
    uint32_t* xh = psm;
    uint32_t* xl = psm + XS_SZ;
    uint32_t* wh = psm + 2 * XS_SZ;
    uint32_t* wl = psm + 2 * XS_SZ + WS_SZ;

    const int row0 = blockIdx.x * 128;
    const int tid = threadIdx.x;
    const int w = tid >> 5;
    const int lane = tid & 31;
    const int g = lane >> 2;
    const int c = lane & 3;
    const int wr = (w & 3) * 32;      // warp row base (0,32,64,96)
    const int wc = (w >> 2) * 48;     // warp col base (0,48,96,144)

    float acc[2][6][4];
#pragma unroll
    for (int mt = 0; mt < 2; mt++)
#pragma unroll
        for (int nb = 0; nb < 6; nb++)
#pragma unroll
            for (int i = 0; i < 4; i++) acc[mt][nb][i] = 0.f;

#pragma unroll 1
    for (int ch = 0; ch < 8; ch++) {
        __syncthreads();   // previous chunk's MMA reads done

        // ---- load + split x chunk [128 x 64]: 2048 float4 / 512 thr ----
#pragma unroll
        for (int it = 0; it < 4; it++) {
            int f = tid + it * 512;
            int r = f >> 4, c4 = (f & 15) << 2;
            float4 v = *(const float4*)&x[(size_t)(row0 + r) * CC + ch * 64 + c4];
            uint4 uh, ul;
            tf_split(v.x, uh.x, ul.x);
            tf_split(v.y, uh.y, ul.y);
            tf_split(v.z, uh.z, ul.z);
            tf_split(v.w, uh.w, ul.w);
            *(uint4*)&xh[r * PX + c4] = uh;
            *(uint4*)&xl[r * PX + c4] = ul;
        }
        // ---- load + split W chunk [64 x 192] (Wk|Wq|Wv): 3072 float4 ----
#pragma unroll
        for (int it = 0; it < 6; it++) {
            int f = tid + it * 512;
            int r = f / 48, c4 = (f % 48) << 2;
            const float* src;
            if (c4 < 64)       src = Wk + (size_t)(ch * 64 + r) * HD + c4;
            else if (c4 < 128) src = Wq + (size_t)(ch * 64 + r) * HD + (c4 - 64);
            else               src = Wv + (size_t)(ch * 64 + r) * HD + (c4 - 128);
            float4 v = *(const float4*)src;
            uint4 uh, ul;
            tf_split(v.x, uh.x, ul.x);
            tf_split(v.y, uh.y, ul.y);
            tf_split(v.z, uh.z, ul.z);
            tf_split(v.w, uh.w, ul.w);
            *(uint4*)&wh[r * PW + c4] = uh;
            *(uint4*)&wl[r * PW + c4] = ul;
        }
        __syncthreads();

        // ---- 3xTF32 MMA over this chunk ----
#pragma unroll 2
        for (int kk = 0; kk < 8; kk++) {
            uint32_t ah[2][4], al[2][4];
#pragma unroll
            for (int mt = 0; mt < 2; mt++) {
                int r = wr + 16 * mt;
                ah[mt][0] = xh[(r + g) * PX + 8 * kk + c];
                ah[mt][1] = xh[(r + g + 8) * PX + 8 * kk + c];
                ah[mt][2] = xh[(r + g) * PX + 8 * kk + c + 4];
                ah[mt][3] = xh[(r + g + 8) * PX + 8 * kk + c + 4];
                al[mt][0] = xl[(r + g) * PX + 8 * kk + c];
                al[mt][1] = xl[(r + g + 8) * PX + 8 * kk + c];
                al[mt][2] = xl[(r + g) * PX + 8 * kk + c + 4];
                al[mt][3] = xl[(r + g + 8) * PX + 8 * kk + c + 4];
            }
#pragma unroll
            for (int nb = 0; nb < 6; nb++) {
                int bcol = wc + 8 * nb + g;
                uint32_t bh0 = wh[(8 * kk + c) * PW + bcol];
                uint32_t bh1 = wh[(8 * kk + c + 4) * PW + bcol];
                uint32_t bl0 = wl[(8 * kk + c) * PW + bcol];
                uint32_t bl1 = wl[(8 * kk + c + 4) * PW + bcol];
#pragma unroll
                for (int mt = 0; mt < 2; mt++) {
                    mma_tf32(acc[mt][nb][0], acc[mt][nb][1], acc[mt][nb][2], acc[mt][nb][3],
                             ah[mt][0], ah[mt][1], ah[mt][2], ah[mt][3], bh0, bh1);
                    mma_tf32(acc[mt][nb][0], acc[mt][nb][1], acc[mt][nb][2], acc[mt][nb][3],
                             ah[mt][0], ah[mt][1], ah[mt][2], ah[mt][3], bl0, bl1);
                    mma_tf32(acc[mt][nb][0], acc[mt][nb][1], acc[mt][nb][2], acc[mt][nb][3],
                             al[mt][0], al[mt][1], al[mt][2], al[mt][3], bh0, bh1);
                }
            }
        }
    }

    // ---- epilogue: write tf32 bits; q scaled by C^-0.5 * log2(e) ----
    const float qscale = rsqrtf((float)CC) * 1.44269504088896341f;
#pragma unroll
    for (int mt = 0; mt < 2; mt++) {
#pragma unroll
        for (int nb = 0; nb < 6; nb++) {
            int colg = wc + 8 * nb + 2 * c;
            uint32_t* dst;
            float sc;
            if (colg < 64)       { dst = g_k; sc = 1.f; }
            else if (colg < 128) { dst = g_q; sc = qscale; colg -= 64; }
            else                 { dst = g_v; sc = 1.f; colg -= 128; }
            size_t r0 = (size_t)(row0 + wr + 16 * mt + g) * HD + colg;
            size_t r1 = (size_t)(row0 + wr + 16 * mt + g + 8) * HD + colg;
            *(uint2*)&dst[r0] = make_uint2(f2tf(acc[mt][nb][0] * sc), f2tf(acc[mt][nb][1] * sc));
            *(uint2*)&dst[r1] = make_uint2(f2tf(acc[mt][nb][2] * sc), f2tf(acc[mt][nb][3] * sc));
        }
    }
}

// ---------------------------------------------------------------------------
// Flash attention, tf32 mma, split-KV. Inputs already tf32 bits (q pre-scaled).
// ---------------------------------------------------------------------------
__global__ __launch_bounds__(256, 2) void flash_kernel() {
    extern __shared__ uint32_t smem[];
    uint32_t (*Ks)[PAD] = (uint32_t(*)[PAD])(smem);
    uint32_t (*Vs)[PAD] = (uint32_t(*)[PAD])(smem + 64 * PAD);
    uint32_t (*Ps)[PAD] = (uint32_t(*)[PAD])(smem + 2 * 64 * PAD);

    const int rr = NITEMS - 1 - blockIdx.x;
    const int b = rr / NITEMS_PER_B;
    const int r = rr - b * NITEMS_PER_B;
    int qb, sp;
    if (r < 8)       { qb = r;                 sp = 0; }
    else if (r < 24) { qb = 8 + (r - 8) / 2;   sp = (r - 8) & 1; }
    else if (r < 48) { qb = 16 + (r - 24) / 3; sp = (r - 24) % 3; }
    else             { qb = 24 + (r - 48) / 4; sp = (r - 48) & 3; }

    const int n_tiles = 2 * qb + 2;
    const int jb_lo = sp * SPLIT;
    const int jb_hi = min(jb_lo + SPLIT, n_tiles);

    const int tid = threadIdx.x;
    const int w = tid >> 5;
    const int lane = tid & 31;
    const int g = lane >> 2;
    const int c = lane & 3;

    // stage Q into Ps (already tf32 + scaled)
    const uint32_t* Qg = g_q + ((size_t)b * TT + (size_t)qb * BM) * HD;
#pragma unroll
    for (int it = 0; it < 8; it++) {
        int f = tid + it * 256;
        int row = f >> 4, c4 = (f & 15) << 2;
        *(uint4*)&Ps[row][c4] = *(const uint4*)&Qg[(size_t)row * HD + c4];
    }
    __syncthreads();

    uint32_t qf[8][4];
#pragma unroll
    for (int kk = 0; kk < 8; kk++) {
        qf[kk][0] = Ps[16 * w + g][8 * kk + c];
        qf[kk][1] = Ps[16 * w + g + 8][8 * kk + c];
        qf[kk][2] = Ps[16 * w + g][8 * kk + c + 4];
        qf[kk][3] = Ps[16 * w + g + 8][8 * kk + c + 4];
    }

    float o[8][4];
#pragma unroll
    for (int nb = 0; nb < 8; nb++)
#pragma unroll
        for (int i = 0; i < 4; i++) o[nb][i] = 0.f;
    float m0 = -INFINITY, m1 = -INFINITY, l0 = 0.f, l1 = 0.f;

    for (int jb = jb_lo; jb < jb_hi; jb++) {
        const uint32_t* Kg = g_k + ((size_t)b * TT + (size_t)jb * BN) * HD;
        const uint32_t* Vg = g_v + ((size_t)b * TT + (size_t)jb * BN) * HD;

        __syncthreads();
#pragma unroll
        for (int it = 0; it < 4; it++) {
            int f = tid + it * 256;
            int row = f >> 4, c4 = (f & 15) << 2;
            *(uint4*)&Ks[row][c4] = *(const uint4*)&Kg[(size_t)row * HD + c4];
            *(uint4*)&Vs[row][c4] = *(const uint4*)&Vg[(size_t)row * HD + c4];
        }
        __syncthreads();

        // ---- S = Q K^T ----
        float s[8][4];
#pragma unroll
        for (int nb = 0; nb < 8; nb++) {
            s[nb][0] = s[nb][1] = s[nb][2] = s[nb][3] = 0.f;
#pragma unroll
            for (int kk = 0; kk < 8; kk++) {
                uint32_t b0 = Ks[8 * nb + g][8 * kk + c];
                uint32_t b1 = Ks[8 * nb + g][8 * kk + c + 4];
                mma_tf32(s[nb][0], s[nb][1], s[nb][2], s[nb][3],
                         qf[kk][0], qf[kk][1], qf[kk][2], qf[kk][3], b0, b1);
            }
        }

        if (jb >= n_tiles - 2) {
            const int row0g = qb * BM + 16 * w + g;
            const int col0g = jb * BN + 2 * c;
#pragma unroll
            for (int nb = 0; nb < 8; nb++) {
                int cg = col0g + 8 * nb;
                if (cg     > row0g)     s[nb][0] = -INFINITY;
                if (cg + 1 > row0g)     s[nb][1] = -INFINITY;
                if (cg     > row0g + 8) s[nb][2] = -INFINITY;
                if (cg + 1 > row0g + 8) s[nb][3] = -INFINITY;
            }
        }

        // ---- online softmax (base-2) ----
        float mx0 = -INFINITY, mx1 = -INFINITY;
#pragma unroll
        for (int nb = 0; nb < 8; nb++) {
            mx0 = fmaxf(mx0, fmaxf(s[nb][0], s[nb][1]));
            mx1 = fmaxf(mx1, fmaxf(s[nb][2], s[nb][3]));
        }
#pragma unroll
        for (int off = 1; off <= 2; off <<= 1) {
            mx0 = fmaxf(mx0, __shfl_xor_sync(0xffffffffu, mx0, off));
            mx1 = fmaxf(mx1, __shfl_xor_sync(0xffffffffu, mx1, off));
        }
        float mn0 = fmaxf(m0, mx0), mn1 = fmaxf(m1, mx1);
        float a0 = exp2f(m0 - mn0), a1 = exp2f(m1 - mn1);
        m0 = mn0; m1 = mn1;

        float rs0 = 0.f, rs1 = 0.f;
#pragma unroll
        for (int nb = 0; nb < 8; nb++) {
            float p0 = exp2f(s[nb][0] - m0);
            float p1 = exp2f(s[nb][1] - m0);
            float p2 = exp2f(s[nb][2] - m1);
            float p3 = exp2f(s[nb][3] - m1);
            rs0 += p0 + p1; rs1 += p2 + p3;
            Ps[16 * w + g][8 * nb + 2 * c]         = f2tf(p0);
            Ps[16 * w + g][8 * nb + 2 * c + 1]     = f2tf(p1);
            Ps[16 * w + g + 8][8 * nb + 2 * c]     = f2tf(p2);
            Ps[16 * w + g + 8][8 * nb + 2 * c + 1] = f2tf(p3);
        }
#pragma unroll
        for (int off = 1; off <= 2; off <<= 1) {
            rs0 += __shfl_xor_sync(0xffffffffu, rs0, off);
            rs1 += __shfl_xor_sync(0xffffffffu, rs1, off);
        }
        l0 = l0 * a0 + rs0;
        l1 = l1 * a1 + rs1;
#pragma unroll
        for (int nb = 0; nb < 8; nb++) {
            o[nb][0] *= a0; o[nb][1] *= a0;
            o[nb][2] *= a1; o[nb][3] *= a1;
        }
        __syncwarp();

        // ---- O += P V ----
#pragma unroll
        for (int kk = 0; kk < 8; kk++) {
            uint32_t pa0 = Ps[16 * w + g][8 * kk + c];
            uint32_t pa1 = Ps[16 * w + g + 8][8 * kk + c];
            uint32_t pa2 = Ps[16 * w + g][8 * kk + c + 4];
            uint32_t pa3 = Ps[16 * w + g + 8][8 * kk + c + 4];
#pragma unroll
            for (int nb = 0; nb < 8; nb++) {
                uint32_t b0 = Vs[8 * kk + c][8 * nb + g];
                uint32_t b1 = Vs[8 * kk + c + 4][8 * nb + g];
                mma_tf32(o[nb][0], o[nb][1], o[nb][2], o[nb][3],
                         pa0, pa1, pa2, pa3, b0, b1);
            }
        }
    }

    // ---- write partials ----
    const int p = ((b * QB_PER_B + qb) << 2) + sp;
    float* pacc = g_pacc + (size_t)p * BM * HD;
    const int r0 = 16 * w + g;
#pragma unroll
    for (int nb = 0; nb < 8; nb++) {
        *(float2*)&pacc[(size_t)r0 * HD + 8 * nb + 2 * c]       = make_float2(o[nb][0], o[nb][1]);
        *(float2*)&pacc[(size_t)(r0 + 8) * HD + 8 * nb + 2 * c] = make_float2(o[nb][2], o[nb][3]);
    }
    if (c == 0) {
        g_pm[p * BM + r0] = m0;     g_pm[p * BM + r0 + 8] = m1;
        g_pl[p * BM + r0] = l0;     g_pl[p * BM + r0 + 8] = l1;
    }
}

// ---------------------------------------------------------------------------
__global__ __launch_bounds__(256) void combine_kernel(float* __restrict__ out) {
    __shared__ float wsm[4][BM];
    __shared__ float linv[BM];

    const int bq = blockIdx.x;
    const int b = bq >> 5;
    const int qb = bq & 31;
    const int nS = qb / 8 + 1;
    const int tid = threadIdx.x;
    const int pbase = bq << 2;

    if (tid < BM) {
        float M = -INFINITY;
        for (int s = 0; s < nS; s++)
            M = fmaxf(M, g_pm[(pbase + s) * BM + tid]);
        float L = 0.f;
        for (int s = 0; s < nS; s++) {
            float wgt = exp2f(g_pm[(pbase + s) * BM + tid] - M);
            wsm[s][tid] = wgt;
            L += g_pl[(pbase + s) * BM + tid] * wgt;
        }
        linv[tid] = 1.0f / L;
    }
    __syncthreads();

    float* og = out + ((size_t)b * TT + (size_t)qb * BM) * HD;
#pragma unroll
    for (int e = 0; e < 32; e++) {
        int flat = tid + e * 256;
        int row = flat >> 6;
        float sum = 0.f;
        for (int s = 0; s < nS; s++)
            sum += g_pacc[(size_t)(pbase + s) * BM * HD + flat] * wsm[s][row];
        og[flat] = sum * linv[row];
    }
}

// ---------------------------------------------------------------------------
extern "C" void kernel_launch(void* const* d_in, const int* in_sizes, int n_in,
                              void* d_out, int out_size) {
    const float* x  = (const float*)d_in[0];
    const float* Wk = (const float*)d_in[1];
    const float* Wq = (const float*)d_in[2];
    const float* Wv = (const float*)d_in[3];
    float* out = (float*)d_out;
    (void)in_sizes; (void)n_in; (void)out_size;

    const int proj_smem = 2 * (XS_SZ + WS_SZ) * (int)sizeof(uint32_t);      // 172032
    const int flash_smem = (64 + 64 + 128) * PAD * (int)sizeof(uint32_t);   // 69632
    static int attr_set = 0;
    if (!attr_set) {
        cudaFuncSetAttribute(proj_kernel,
                             cudaFuncAttributeMaxDynamicSharedMemorySize, proj_smem);
        cudaFuncSetAttribute(flash_kernel,
                             cudaFuncAttributeMaxDynamicSharedMemorySize, flash_smem);
        attr_set = 1;
    }

    proj_kernel<<<128, 512, proj_smem>>>(x, Wk, Wq, Wv);
    flash_kernel<<<NITEMS, 256, flash_smem>>>();
    combine_kernel<<<128, 256>>>(out);
}

// round 7
// speedup vs baseline: 1.5164x; 1.5164x over previous
#include <cuda_runtime.h>
#include <math.h>
#include <stdint.h>

#define BB 4
#define TT 4096
#define CC 512
#define HD 64

#define BM 128           // q-tile rows per flash CTA
#define BN 64            // kv-tile rows
#define SPLIT 16         // max KV tiles per work item
#define QB_PER_B 32      // TT / BM
#define NITEMS_PER_B 80
#define NITEMS (BB * NITEMS_PER_B)   // 320
#define PAD 68           // flash smem row stride (u32)

// q/k/v stored as tf32 bit patterns (q pre-scaled by C^-0.5 * log2e)
__device__ uint32_t g_q[BB * TT * HD];
__device__ uint32_t g_k[BB * TT * HD];
__device__ uint32_t g_v[BB * TT * HD];

// pre-split W (hi/lo tf32 bits): [512 k][192 cols = Wk|Wq|Wv]
__device__ uint32_t g_wh[CC * 192];
__device__ uint32_t g_wl[CC * 192];

// split-KV partials
__device__ float g_pacc[BB * QB_PER_B * 4 * BM * HD];
__device__ float g_pm[BB * QB_PER_B * 4 * BM];
__device__ float g_pl[BB * QB_PER_B * 4 * BM];

__device__ __forceinline__ uint32_t f2tf(float f) {
    uint32_t u;
    asm("cvt.rna.tf32.f32 %0, %1;" : "=r"(u) : "f"(f));
    return u;
}

__device__ __forceinline__ void mma_tf32(float& d0, float& d1, float& d2, float& d3,
                                         uint32_t a0, uint32_t a1, uint32_t a2, uint32_t a3,
                                         uint32_t b0, uint32_t b1) {
    asm volatile(
        "mma.sync.aligned.m16n8k8.row.col.f32.tf32.tf32.f32 "
        "{%0,%1,%2,%3}, {%4,%5,%6,%7}, {%8,%9}, {%0,%1,%2,%3};"
        : "+f"(d0), "+f"(d1), "+f"(d2), "+f"(d3)
        : "r"(a0), "r"(a1), "r"(a2), "r"(a3), "r"(b0), "r"(b1));
}

__device__ __forceinline__ void tf_split(float v, uint32_t& hi, uint32_t& lo) {
    hi = f2tf(v);
    float hif = __uint_as_float(hi);
    lo = f2tf(v - hif);
}

__device__ __forceinline__ uint32_t smem_u32(const void* p) {
    return (uint32_t)__cvta_generic_to_shared(p);
}
__device__ __forceinline__ void cp_async16(uint32_t dst, const void* src) {
    asm volatile("cp.async.ca.shared.global [%0], [%1], 16;" :: "r"(dst), "l"(src));
}
__device__ __forceinline__ void cp_commit() {
    asm volatile("cp.async.commit_group;");
}
template <int N>
__device__ __forceinline__ void cp_wait() {
    asm volatile("cp.async.wait_group %0;" :: "n"(N));
}

// ---------------------------------------------------------------------------
// Prep: split W (Wk|Wq|Wv -> [512][192]) into hi/lo tf32 bits.
// 24576 float4s, 96 blocks x 256 threads.
// ---------------------------------------------------------------------------
__global__ __launch_bounds__(256) void prep_kernel(const float* __restrict__ Wk,
                                                   const float* __restrict__ Wq,
                                                   const float* __restrict__ Wv) {
    int idx = blockIdx.x * 256 + threadIdx.x;       // float4 index, < 512*48
    if (idx >= CC * 48) return;
    int k = idx / 48;
    int c4 = (idx % 48) << 2;                       // 0..188
    const float* src;
    if (c4 < 64)       src = Wk + (size_t)k * HD + c4;
    else if (c4 < 128) src = Wq + (size_t)k * HD + (c4 - 64);
    else               src = Wv + (size_t)k * HD + (c4 - 128);
    float4 v = *(const float4*)src;
    uint4 uh, ul;
    tf_split(v.x, uh.x, ul.x);
    tf_split(v.y, uh.y, ul.y);
    tf_split(v.z, uh.z, ul.z);
    tf_split(v.w, uh.w, ul.w);
    *(uint4*)&g_wh[k * 192 + c4] = uh;
    *(uint4*)&g_wl[k * 192 + c4] = ul;
}

// ---------------------------------------------------------------------------
// Fused projection GEMM (3xTF32): [16384x512] @ [512x192]
// 128 CTAs x 512 thr (16 warps); warp w: rows 32*(w&3), cols 48*(w>>2).
// K-chunks of 32, cp.async double-buffered. x staged raw (split in regs);
// W hi/lo from pre-split scratch. smem = 139264 B.
// ---------------------------------------------------------------------------
#define KC 32
#define PXS 36                // x raw row stride
#define PWS 200               // W hi/lo row stride
#define XRSZ (128 * PXS)      // 4608
#define WSZ (KC * PWS)        // 6400

__global__ __launch_bounds__(512, 1) void proj_kernel(const float* __restrict__ x) {
    extern __shared__ uint32_t psm[];
    uint32_t* xrb[2] = { psm, psm + XRSZ };
    uint32_t* whb[2] = { psm + 2 * XRSZ, psm + 2 * XRSZ + WSZ };
    uint32_t* wlb[2] = { psm + 2 * XRSZ + 2 * WSZ, psm + 2 * XRSZ + 3 * WSZ };

    const int row0 = blockIdx.x * 128;
    const int tid = threadIdx.x;
    const int w = tid >> 5;
    const int lane = tid & 31;
    const int g = lane >> 2;
    const int c = lane & 3;
    const int wr = (w & 3) * 32;      // warp row base (0,32,64,96)
    const int wc = (w >> 2) * 48;     // warp col base (0,48,96,144)

    auto load_chunk = [&](int ch, int bi) {
        // x raw chunk [128 x 32]: 1024 16B
#pragma unroll
        for (int it = 0; it < 2; it++) {
            int f = tid + it * 512;
            int r = f >> 3, c4 = (f & 7) << 2;
            cp_async16(smem_u32(&xrb[bi][r * PXS + c4]),
                       &x[(size_t)(row0 + r) * CC + ch * KC + c4]);
        }
        // W hi+lo chunk [32 x 192] each: 1536 + 1536 16B
#pragma unroll
        for (int it = 0; it < 6; it++) {
            int f = tid + it * 512;
            if (f < 1536) {
                int r = f / 48, c4 = (f % 48) << 2;
                cp_async16(smem_u32(&whb[bi][r * PWS + c4]),
                           &g_wh[(size_t)(ch * KC + r) * 192 + c4]);
            } else {
                int f2 = f - 1536;
                int r = f2 / 48, c4 = (f2 % 48) << 2;
                cp_async16(smem_u32(&wlb[bi][r * PWS + c4]),
                           &g_wl[(size_t)(ch * KC + r) * 192 + c4]);
            }
        }
        cp_commit();
    };

    float acc[2][6][4];
#pragma unroll
    for (int mt = 0; mt < 2; mt++)
#pragma unroll
        for (int nb = 0; nb < 6; nb++)
#pragma unroll
            for (int i = 0; i < 4; i++) acc[mt][nb][i] = 0.f;

    load_chunk(0, 0);

#pragma unroll 1
    for (int ch = 0; ch < CC / KC; ch++) {
        const int bi = ch & 1;
        __syncthreads();                       // all warps done reading buf bi^1
        if (ch + 1 < CC / KC) {
            load_chunk(ch + 1, bi ^ 1);
            cp_wait<1>();
        } else {
            cp_wait<0>();
        }
        __syncthreads();                       // buf bi visible to all

        const uint32_t* xr = xrb[bi];
        const uint32_t* wh = whb[bi];
        const uint32_t* wl = wlb[bi];
#pragma unroll
        for (int kk = 0; kk < KC / 8; kk++) {
            uint32_t ah[2][4], al[2][4];
#pragma unroll
            for (int mt = 0; mt < 2; mt++) {
                int r = wr + 16 * mt;
                float v0 = __uint_as_float(xr[(r + g) * PXS + 8 * kk + c]);
                float v1 = __uint_as_float(xr[(r + g + 8) * PXS + 8 * kk + c]);
                float v2 = __uint_as_float(xr[(r + g) * PXS + 8 * kk + c + 4]);
                float v3 = __uint_as_float(xr[(r + g + 8) * PXS + 8 * kk + c + 4]);
                tf_split(v0, ah[mt][0], al[mt][0]);
                tf_split(v1, ah[mt][1], al[mt][1]);
                tf_split(v2, ah[mt][2], al[mt][2]);
                tf_split(v3, ah[mt][3], al[mt][3]);
            }
#pragma unroll
            for (int nb = 0; nb < 6; nb++) {
                int bcol = wc + 8 * nb + g;
                uint32_t bh0 = wh[(8 * kk + c) * PWS + bcol];
                uint32_t bh1 = wh[(8 * kk + c + 4) * PWS + bcol];
                uint32_t bl0 = wl[(8 * kk + c) * PWS + bcol];
                uint32_t bl1 = wl[(8 * kk + c + 4) * PWS + bcol];
#pragma unroll
                for (int mt = 0; mt < 2; mt++) {
                    mma_tf32(acc[mt][nb][0], acc[mt][nb][1], acc[mt][nb][2], acc[mt][nb][3],
                             ah[mt][0], ah[mt][1], ah[mt][2], ah[mt][3], bh0, bh1);
                    mma_tf32(acc[mt][nb][0], acc[mt][nb][1], acc[mt][nb][2], acc[mt][nb][3],
                             ah[mt][0], ah[mt][1], ah[mt][2], ah[mt][3], bl0, bl1);
                    mma_tf32(acc[mt][nb][0], acc[mt][nb][1], acc[mt][nb][2], acc[mt][nb][3],
                             al[mt][0], al[mt][1], al[mt][2], al[mt][3], bh0, bh1);
                }
            }
        }
    }

    // ---- epilogue: write tf32 bits; q scaled by C^-0.5 * log2(e) ----
    const float qscale = rsqrtf((float)CC) * 1.44269504088896341f;
#pragma unroll
    for (int mt = 0; mt < 2; mt++) {
#pragma unroll
        for (int nb = 0; nb < 6; nb++) {
            int colg = wc + 8 * nb + 2 * c;
            uint32_t* dst;
            float sc;
            if (colg < 64)       { dst = g_k; sc = 1.f; }
            else if (colg < 128) { dst = g_q; sc = qscale; colg -= 64; }
            else                 { dst = g_v; sc = 1.f; colg -= 128; }
            size_t r0 = (size_t)(row0 + wr + 16 * mt + g) * HD + colg;
            size_t r1 = (size_t)(row0 + wr + 16 * mt + g + 8) * HD + colg;
            *(uint2*)&dst[r0] = make_uint2(f2tf(acc[mt][nb][0] * sc), f2tf(acc[mt][nb][1] * sc));
            *(uint2*)&dst[r1] = make_uint2(f2tf(acc[mt][nb][2] * sc), f2tf(acc[mt][nb][3] * sc));
        }
    }
}

// ---------------------------------------------------------------------------
// Flash attention, tf32 mma, split-KV, cp.async double-buffered K/V.
// smem: KV buf0 | KV buf1 | Ps  = (2*2*64 + 128) * PAD u32 = 104448 B
// ---------------------------------------------------------------------------
#define KVBUF (2 * 64 * PAD)

__global__ __launch_bounds__(256, 2) void flash_kernel() {
    extern __shared__ uint32_t smem[];
    uint32_t (*Ps)[PAD] = (uint32_t(*)[PAD])(smem + 2 * KVBUF);

    const int rr = NITEMS - 1 - blockIdx.x;
    const int b = rr / NITEMS_PER_B;
    const int r = rr - b * NITEMS_PER_B;
    int qb, sp;
    if (r < 8)       { qb = r;                 sp = 0; }
    else if (r < 24) { qb = 8 + (r - 8) / 2;   sp = (r - 8) & 1; }
    else if (r < 48) { qb = 16 + (r - 24) / 3; sp = (r - 24) % 3; }
    else             { qb = 24 + (r - 48) / 4; sp = (r - 48) & 3; }

    const int n_tiles = 2 * qb + 2;
    const int jb_lo = sp * SPLIT;
    const int jb_hi = min(jb_lo + SPLIT, n_tiles);

    const int tid = threadIdx.x;
    const int w = tid >> 5;
    const int lane = tid & 31;
    const int g = lane >> 2;
    const int c = lane & 3;

    auto kv_load = [&](int jb, int bi) {
        const uint32_t* Kg = g_k + ((size_t)b * TT + (size_t)jb * BN) * HD;
        const uint32_t* Vg = g_v + ((size_t)b * TT + (size_t)jb * BN) * HD;
        uint32_t* Kd = smem + bi * KVBUF;
        uint32_t* Vd = Kd + 64 * PAD;
#pragma unroll
        for (int it = 0; it < 4; it++) {
            int f = tid + it * 256;
            int row = f >> 4, c4 = (f & 15) << 2;
            cp_async16(smem_u32(&Kd[row * PAD + c4]), &Kg[(size_t)row * HD + c4]);
            cp_async16(smem_u32(&Vd[row * PAD + c4]), &Vg[(size_t)row * HD + c4]);
        }
        cp_commit();
    };

    // ---- prologue: Q into Ps (group 0), first KV tile (group 1) ----
    const uint32_t* Qg = g_q + ((size_t)b * TT + (size_t)qb * BM) * HD;
#pragma unroll
    for (int it = 0; it < 8; it++) {
        int f = tid + it * 256;
        int row = f >> 4, c4 = (f & 15) << 2;
        cp_async16(smem_u32(&Ps[row][c4]), &Qg[(size_t)row * HD + c4]);
    }
    cp_commit();
    kv_load(jb_lo, 0);
    cp_wait<1>();           // Q ready
    __syncthreads();

    uint32_t qf[8][4];
#pragma unroll
    for (int kk = 0; kk < 8; kk++) {
        qf[kk][0] = Ps[16 * w + g][8 * kk + c];
        qf[kk][1] = Ps[16 * w + g + 8][8 * kk + c];
        qf[kk][2] = Ps[16 * w + g][8 * kk + c + 4];
        qf[kk][3] = Ps[16 * w + g + 8][8 * kk + c + 4];
    }

    float o[8][4];
#pragma unroll
    for (int nb = 0; nb < 8; nb++)
#pragma unroll
        for (int i = 0; i < 4; i++) o[nb][i] = 0.f;
    float m0 = -INFINITY, m1 = -INFINITY, l0 = 0.f, l1 = 0.f;

#pragma unroll 1
    for (int jb = jb_lo; jb < jb_hi; jb++) {
        const int bi = (jb - jb_lo) & 1;
        __syncthreads();                  // all warps done reading buf bi^1
        if (jb + 1 < jb_hi) {
            kv_load(jb + 1, bi ^ 1);
            cp_wait<1>();
        } else {
            cp_wait<0>();
        }
        __syncthreads();                  // buf bi visible

        const uint32_t (*Ks)[PAD] = (const uint32_t(*)[PAD])(smem + bi * KVBUF);
        const uint32_t (*Vs)[PAD] = (const uint32_t(*)[PAD])(smem + bi * KVBUF + 64 * PAD);

        // ---- S = Q K^T ----
        float s[8][4];
#pragma unroll
        for (int nb = 0; nb < 8; nb++) {
            s[nb][0] = s[nb][1] = s[nb][2] = s[nb][3] = 0.f;
#pragma unroll
            for (int kk = 0; kk < 8; kk++) {
                uint32_t b0 = Ks[8 * nb + g][8 * kk + c];
                uint32_t b1 = Ks[8 * nb + g][8 * kk + c + 4];
                mma_tf32(s[nb][0], s[nb][1], s[nb][2], s[nb][3],
                         qf[kk][0], qf[kk][1], qf[kk][2], qf[kk][3], b0, b1);
            }
        }

        if (jb >= n_tiles - 2) {          // causal mask (diagonal tiles)
            const int row0g = qb * BM + 16 * w + g;
            const int col0g = jb * BN + 2 * c;
#pragma unroll
            for (int nb = 0; nb < 8; nb++) {
                int cg = col0g + 8 * nb;
                if (cg     > row0g)     s[nb][0] = -INFINITY;
                if (cg + 1 > row0g)     s[nb][1] = -INFINITY;
                if (cg     > row0g + 8) s[nb][2] = -INFINITY;
                if (cg + 1 > row0g + 8) s[nb][3] = -INFINITY;
            }
        }

        // ---- online softmax (base-2) ----
        float mx0 = -INFINITY, mx1 = -INFINITY;
#pragma unroll
        for (int nb = 0; nb < 8; nb++) {
            mx0 = fmaxf(mx0, fmaxf(s[nb][0], s[nb][1]));
            mx1 = fmaxf(mx1, fmaxf(s[nb][2], s[nb][3]));
        }
#pragma unroll
        for (int off = 1; off <= 2; off <<= 1) {
            mx0 = fmaxf(mx0, __shfl_xor_sync(0xffffffffu, mx0, off));
            mx1 = fmaxf(mx1, __shfl_xor_sync(0xffffffffu, mx1, off));
        }
        float mn0 = fmaxf(m0, mx0), mn1 = fmaxf(m1, mx1);
        float a0 = exp2f(m0 - mn0), a1 = exp2f(m1 - mn1);
        m0 = mn0; m1 = mn1;

        float rs0 = 0.f, rs1 = 0.f;
#pragma unroll
        for (int nb = 0; nb < 8; nb++) {
            float p0 = exp2f(s[nb][0] - m0);
            float p1 = exp2f(s[nb][1] - m0);
            float p2 = exp2f(s[nb][2] - m1);
            float p3 = exp2f(s[nb][3] - m1);
            rs0 += p0 + p1; rs1 += p2 + p3;
            Ps[16 * w + g][8 * nb + 2 * c]         = f2tf(p0);
            Ps[16 * w + g][8 * nb + 2 * c + 1]     = f2tf(p1);
            Ps[16 * w + g + 8][8 * nb + 2 * c]     = f2tf(p2);
            Ps[16 * w + g + 8][8 * nb + 2 * c + 1] = f2tf(p3);
        }
#pragma unroll
        for (int off = 1; off <= 2; off <<= 1) {
            rs0 += __shfl_xor_sync(0xffffffffu, rs0, off);
            rs1 += __shfl_xor_sync(0xffffffffu, rs1, off);
        }
        l0 = l0 * a0 + rs0;
        l1 = l1 * a1 + rs1;
#pragma unroll
        for (int nb = 0; nb < 8; nb++) {
            o[nb][0] *= a0; o[nb][1] *= a0;
            o[nb][2] *= a1; o[nb][3] *= a1;
        }
        __syncwarp();                     // Ps rows warp-private

        // ---- O += P V ----
#pragma unroll
        for (int kk = 0; kk < 8; kk++) {
            uint32_t pa0 = Ps[16 * w + g][8 * kk + c];
            uint32_t pa1 = Ps[16 * w + g + 8][8 * kk + c];
            uint32_t pa2 = Ps[16 * w + g][8 * kk + c + 4];
            uint32_t pa3 = Ps[16 * w + g + 8][8 * kk + c + 4];
#pragma unroll
            for (int nb = 0; nb < 8; nb++) {
                uint32_t b0 = Vs[8 * kk + c][8 * nb + g];
                uint32_t b1 = Vs[8 * kk + c + 4][8 * nb + g];
                mma_tf32(o[nb][0], o[nb][1], o[nb][2], o[nb][3],
                         pa0, pa1, pa2, pa3, b0, b1);
            }
        }
    }

    // ---- write partials ----
    const int p = ((b * QB_PER_B + qb) << 2) + sp;
    float* pacc = g_pacc + (size_t)p * BM * HD;
    const int r0 = 16 * w + g;
#pragma unroll
    for (int nb = 0; nb < 8; nb++) {
        *(float2*)&pacc[(size_t)r0 * HD + 8 * nb + 2 * c]       = make_float2(o[nb][0], o[nb][1]);
        *(float2*)&pacc[(size_t)(r0 + 8) * HD + 8 * nb + 2 * c] = make_float2(o[nb][2], o[nb][3]);
    }
    if (c == 0) {
        g_pm[p * BM + r0] = m0;     g_pm[p * BM + r0 + 8] = m1;
        g_pl[p * BM + r0] = l0;     g_pl[p * BM + r0 + 8] = l1;
    }
}

// ---------------------------------------------------------------------------
__global__ __launch_bounds__(256) void combine_kernel(float* __restrict__ out) {
    __shared__ float wsm[4][BM];
    __shared__ float linv[BM];

    const int bq = blockIdx.x;
    const int b = bq >> 5;
    const int qb = bq & 31;
    const int nS = qb / 8 + 1;
    const int tid = threadIdx.x;
    const int pbase = bq << 2;

    if (tid < BM) {
        float M = -INFINITY;
        for (int s = 0; s < nS; s++)
            M = fmaxf(M, g_pm[(pbase + s) * BM + tid]);
        float L = 0.f;
        for (int s = 0; s < nS; s++) {
            float wgt = exp2f(g_pm[(pbase + s) * BM + tid] - M);
            wsm[s][tid] = wgt;
            L += g_pl[(pbase + s) * BM + tid] * wgt;
        }
        linv[tid] = 1.0f / L;
    }
    __syncthreads();

    float* og = out + ((size_t)b * TT + (size_t)qb * BM) * HD;
#pragma unroll
    for (int e = 0; e < 32; e++) {
        int flat = tid + e * 256;
        int row = flat >> 6;
        float sum = 0.f;
        for (int s = 0; s < nS; s++)
            sum += g_pacc[(size_t)(pbase + s) * BM * HD + flat] * wsm[s][row];
        og[flat] = sum * linv[row];
    }
}

// ---------------------------------------------------------------------------
extern "C" void kernel_launch(void* const* d_in, const int* in_sizes, int n_in,
                              void* d_out, int out_size) {
    const float* x  = (const float*)d_in[0];
    const float* Wk = (const float*)d_in[1];
    const float* Wq = (const float*)d_in[2];
    const float* Wv = (const float*)d_in[3];
    float* out = (float*)d_out;
    (void)in_sizes; (void)n_in; (void)out_size;

    const int proj_smem = (2 * XRSZ + 4 * WSZ) * (int)sizeof(uint32_t);     // 139264
    const int flash_smem = (2 * KVBUF + 128 * PAD) * (int)sizeof(uint32_t); // 104448
    cudaFuncSetAttribute(proj_kernel,
                         cudaFuncAttributeMaxDynamicSharedMemorySize, proj_smem);
    cudaFuncSetAttribute(flash_kernel,
                         cudaFuncAttributeMaxDynamicSharedMemorySize, flash_smem);

    prep_kernel<<<96, 256>>>(Wk, Wq, Wv);
    proj_kernel<<<128, 512, proj_smem>>>(x);
    flash_kernel<<<NITEMS, 256, flash_smem>>>();
    combine_kernel<<<128, 256>>>(out);
}

// round 8
// speedup vs baseline: 1.6980x; 1.1197x over previous
#include <cuda_runtime.h>
#include <math.h>
#include <stdint.h>

#define BB 4
#define TT 4096
#define CC 512
#define HD 64

#define BM 128           // q-tile rows per flash CTA
#define BN 64            // kv-tile rows
#define SPLIT 16         // max KV tiles per work item
#define QB_PER_B 32      // TT / BM
#define NITEMS_PER_B 80
#define NITEMS (BB * NITEMS_PER_B)   // 320
#define PAD 68           // flash smem row stride (u32)

// q/k/v stored as tf32 bit patterns (q pre-scaled by C^-0.5 * log2e)
__device__ uint32_t g_q[BB * TT * HD];
__device__ uint32_t g_k[BB * TT * HD];
__device__ uint32_t g_v[BB * TT * HD];

// pre-split W (hi/lo tf32 bits): [512 k][192 cols = Wk|Wq|Wv]
__device__ uint32_t g_wh[CC * 192];
__device__ uint32_t g_wl[CC * 192];

// split-KV partials
__device__ float g_pacc[BB * QB_PER_B * 4 * BM * HD];
__device__ float g_pm[BB * QB_PER_B * 4 * BM];
__device__ float g_pl[BB * QB_PER_B * 4 * BM];

__device__ __forceinline__ uint32_t f2tf(float f) {
    uint32_t u;
    asm("cvt.rna.tf32.f32 %0, %1;" : "=r"(u) : "f"(f));
    return u;
}

__device__ __forceinline__ void mma_tf32(float& d0, float& d1, float& d2, float& d3,
                                         uint32_t a0, uint32_t a1, uint32_t a2, uint32_t a3,
                                         uint32_t b0, uint32_t b1) {
    asm volatile(
        "mma.sync.aligned.m16n8k8.row.col.f32.tf32.tf32.f32 "
        "{%0,%1,%2,%3}, {%4,%5,%6,%7}, {%8,%9}, {%0,%1,%2,%3};"
        : "+f"(d0), "+f"(d1), "+f"(d2), "+f"(d3)
        : "r"(a0), "r"(a1), "r"(a2), "r"(a3), "r"(b0), "r"(b1));
}

__device__ __forceinline__ void tf_split(float v, uint32_t& hi, uint32_t& lo) {
    hi = f2tf(v);
    float hif = __uint_as_float(hi);
    lo = f2tf(v - hif);
}

__device__ __forceinline__ uint32_t smem_u32(const void* p) {
    return (uint32_t)__cvta_generic_to_shared(p);
}
__device__ __forceinline__ void cp_async16(uint32_t dst, const void* src) {
    asm volatile("cp.async.ca.shared.global [%0], [%1], 16;" :: "r"(dst), "l"(src));
}
__device__ __forceinline__ void cp_commit() {
    asm volatile("cp.async.commit_group;");
}
template <int N>
__device__ __forceinline__ void cp_wait() {
    asm volatile("cp.async.wait_group %0;" :: "n"(N));
}

// ---------------------------------------------------------------------------
// Prep: split W (Wk|Wq|Wv -> [512][192]) into hi/lo tf32 bits.
// ---------------------------------------------------------------------------
__global__ __launch_bounds__(256) void prep_kernel(const float* __restrict__ Wk,
                                                   const float* __restrict__ Wq,
                                                   const float* __restrict__ Wv) {
    int idx = blockIdx.x * 256 + threadIdx.x;       // float4 index, < 512*48
    if (idx >= CC * 48) return;
    int k = idx / 48;
    int c4 = (idx % 48) << 2;                       // 0..188
    const float* src;
    if (c4 < 64)       src = Wk + (size_t)k * HD + c4;
    else if (c4 < 128) src = Wq + (size_t)k * HD + (c4 - 64);
    else               src = Wv + (size_t)k * HD + (c4 - 128);
    float4 v = *(const float4*)src;
    uint4 uh, ul;
    tf_split(v.x, uh.x, ul.x);
    tf_split(v.y, uh.y, ul.y);
    tf_split(v.z, uh.z, ul.z);
    tf_split(v.w, uh.w, ul.w);
    *(uint4*)&g_wh[k * 192 + c4] = uh;
    *(uint4*)&g_wl[k * 192 + c4] = ul;
}

// ---------------------------------------------------------------------------
// Fused projection GEMM (3xTF32): [16384x512] @ [512x192]
// ---------------------------------------------------------------------------
#define KC 32
#define PXS 36                // x raw row stride
#define PWS 200               // W hi/lo row stride
#define XRSZ (128 * PXS)      // 4608
#define WSZ (KC * PWS)        // 6400

__global__ __launch_bounds__(512, 1) void proj_kernel(const float* __restrict__ x) {
    extern __shared__ uint32_t psm[];
    uint32_t* xrb[2] = { psm, psm + XRSZ };
    uint32_t* whb[2] = { psm + 2 * XRSZ, psm + 2 * XRSZ + WSZ };
    uint32_t* wlb[2] = { psm + 2 * XRSZ + 2 * WSZ, psm + 2 * XRSZ + 3 * WSZ };

    const int row0 = blockIdx.x * 128;
    const int tid = threadIdx.x;
    const int w = tid >> 5;
    const int lane = tid & 31;
    const int g = lane >> 2;
    const int c = lane & 3;
    const int wr = (w & 3) * 32;      // warp row base (0,32,64,96)
    const int wc = (w >> 2) * 48;     // warp col base (0,48,96,144)

    auto load_chunk = [&](int ch, int bi) {
#pragma unroll
        for (int it = 0; it < 2; it++) {
            int f = tid + it * 512;
            int r = f >> 3, c4 = (f & 7) << 2;
            cp_async16(smem_u32(&xrb[bi][r * PXS + c4]),
                       &x[(size_t)(row0 + r) * CC + ch * KC + c4]);
        }
#pragma unroll
        for (int it = 0; it < 6; it++) {
            int f = tid + it * 512;
            if (f < 1536) {
                int r = f / 48, c4 = (f % 48) << 2;
                cp_async16(smem_u32(&whb[bi][r * PWS + c4]),
                           &g_wh[(size_t)(ch * KC + r) * 192 + c4]);
            } else {
                int f2 = f - 1536;
                int r = f2 / 48, c4 = (f2 % 48) << 2;
                cp_async16(smem_u32(&wlb[bi][r * PWS + c4]),
                           &g_wl[(size_t)(ch * KC + r) * 192 + c4]);
            }
        }
        cp_commit();
    };

    float acc[2][6][4];
#pragma unroll
    for (int mt = 0; mt < 2; mt++)
#pragma unroll
        for (int nb = 0; nb < 6; nb++)
#pragma unroll
            for (int i = 0; i < 4; i++) acc[mt][nb][i] = 0.f;

    load_chunk(0, 0);

#pragma unroll 1
    for (int ch = 0; ch < CC / KC; ch++) {
        const int bi = ch & 1;
        __syncthreads();
        if (ch + 1 < CC / KC) {
            load_chunk(ch + 1, bi ^ 1);
            cp_wait<1>();
        } else {
            cp_wait<0>();
        }
        __syncthreads();

        const uint32_t* xr = xrb[bi];
        const uint32_t* wh = whb[bi];
        const uint32_t* wl = wlb[bi];
#pragma unroll
        for (int kk = 0; kk < KC / 8; kk++) {
            uint32_t ah[2][4], al[2][4];
#pragma unroll
            for (int mt = 0; mt < 2; mt++) {
                int r = wr + 16 * mt;
                float v0 = __uint_as_float(xr[(r + g) * PXS + 8 * kk + c]);
                float v1 = __uint_as_float(xr[(r + g + 8) * PXS + 8 * kk + c]);
                float v2 = __uint_as_float(xr[(r + g) * PXS + 8 * kk + c + 4]);
                float v3 = __uint_as_float(xr[(r + g + 8) * PXS + 8 * kk + c + 4]);
                tf_split(v0, ah[mt][0], al[mt][0]);
                tf_split(v1, ah[mt][1], al[mt][1]);
                tf_split(v2, ah[mt][2], al[mt][2]);
                tf_split(v3, ah[mt][3], al[mt][3]);
            }
#pragma unroll
            for (int nb = 0; nb < 6; nb++) {
                int bcol = wc + 8 * nb + g;
                uint32_t bh0 = wh[(8 * kk + c) * PWS + bcol];
                uint32_t bh1 = wh[(8 * kk + c + 4) * PWS + bcol];
                uint32_t bl0 = wl[(8 * kk + c) * PWS + bcol];
                uint32_t bl1 = wl[(8 * kk + c + 4) * PWS + bcol];
#pragma unroll
                for (int mt = 0; mt < 2; mt++) {
                    mma_tf32(acc[mt][nb][0], acc[mt][nb][1], acc[mt][nb][2], acc[mt][nb][3],
                             ah[mt][0], ah[mt][1], ah[mt][2], ah[mt][3], bh0, bh1);
                    mma_tf32(acc[mt][nb][0], acc[mt][nb][1], acc[mt][nb][2], acc[mt][nb][3],
                             ah[mt][0], ah[mt][1], ah[mt][2], ah[mt][3], bl0, bl1);
                    mma_tf32(acc[mt][nb][0], acc[mt][nb][1], acc[mt][nb][2], acc[mt][nb][3],
                             al[mt][0], al[mt][1], al[mt][2], al[mt][3], bh0, bh1);
                }
            }
        }
    }

    const float qscale = rsqrtf((float)CC) * 1.44269504088896341f;
#pragma unroll
    for (int mt = 0; mt < 2; mt++) {
#pragma unroll
        for (int nb = 0; nb < 6; nb++) {
            int colg = wc + 8 * nb + 2 * c;
            uint32_t* dst;
            float sc;
            if (colg < 64)       { dst = g_k; sc = 1.f; }
            else if (colg < 128) { dst = g_q; sc = qscale; colg -= 64; }
            else                 { dst = g_v; sc = 1.f; colg -= 128; }
            size_t r0 = (size_t)(row0 + wr + 16 * mt + g) * HD + colg;
            size_t r1 = (size_t)(row0 + wr + 16 * mt + g + 8) * HD + colg;
            *(uint2*)&dst[r0] = make_uint2(f2tf(acc[mt][nb][0] * sc), f2tf(acc[mt][nb][1] * sc));
            *(uint2*)&dst[r1] = make_uint2(f2tf(acc[mt][nb][2] * sc), f2tf(acc[mt][nb][3] * sc));
        }
    }
}

// ---------------------------------------------------------------------------
// Flash attention, tf32 mma, split-KV, cp.async double-buffered K/V.
// ---------------------------------------------------------------------------
#define KVBUF (2 * 64 * PAD)

__global__ __launch_bounds__(256, 2) void flash_kernel() {
    extern __shared__ uint32_t smem[];
    uint32_t (*Ps)[PAD] = (uint32_t(*)[PAD])(smem + 2 * KVBUF);

    const int rr = NITEMS - 1 - blockIdx.x;
    const int b = rr / NITEMS_PER_B;
    const int r = rr - b * NITEMS_PER_B;
    int qb, sp;
    if (r < 8)       { qb = r;                 sp = 0; }
    else if (r < 24) { qb = 8 + (r - 8) / 2;   sp = (r - 8) & 1; }
    else if (r < 48) { qb = 16 + (r - 24) / 3; sp = (r - 24) % 3; }
    else             { qb = 24 + (r - 48) / 4; sp = (r - 48) & 3; }

    const int n_tiles = 2 * qb + 2;
    const int jb_lo = sp * SPLIT;
    const int jb_hi = min(jb_lo + SPLIT, n_tiles);

    const int tid = threadIdx.x;
    const int w = tid >> 5;
    const int lane = tid & 31;
    const int g = lane >> 2;
    const int c = lane & 3;

    auto kv_load = [&](int jb, int bi) {
        const uint32_t* Kg = g_k + ((size_t)b * TT + (size_t)jb * BN) * HD;
        const uint32_t* Vg = g_v + ((size_t)b * TT + (size_t)jb * BN) * HD;
        uint32_t* Kd = smem + bi * KVBUF;
        uint32_t* Vd = Kd + 64 * PAD;
#pragma unroll
        for (int it = 0; it < 4; it++) {
            int f = tid + it * 256;
            int row = f >> 4, c4 = (f & 15) << 2;
            cp_async16(smem_u32(&Kd[row * PAD + c4]), &Kg[(size_t)row * HD + c4]);
            cp_async16(smem_u32(&Vd[row * PAD + c4]), &Vg[(size_t)row * HD + c4]);
        }
        cp_commit();
    };

    const uint32_t* Qg = g_q + ((size_t)b * TT + (size_t)qb * BM) * HD;
#pragma unroll
    for (int it = 0; it < 8; it++) {
        int f = tid + it * 256;
        int row = f >> 4, c4 = (f & 15) << 2;
        cp_async16(smem_u32(&Ps[row][c4]), &Qg[(size_t)row * HD + c4]);
    }
    cp_commit();
    kv_load(jb_lo, 0);
    cp_wait<1>();           // Q ready
    __syncthreads();

    uint32_t qf[8][4];
#pragma unroll
    for (int kk = 0; kk < 8; kk++) {
        qf[kk][0] = Ps[16 * w + g][8 * kk + c];
        qf[kk][1] = Ps[16 * w + g + 8][8 * kk + c];
        qf[kk][2] = Ps[16 * w + g][8 * kk + c + 4];
        qf[kk][3] = Ps[16 * w + g + 8][8 * kk + c + 4];
    }

    float o[8][4];
#pragma unroll
    for (int nb = 0; nb < 8; nb++)
#pragma unroll
        for (int i = 0; i < 4; i++) o[nb][i] = 0.f;
    float m0 = -INFINITY, m1 = -INFINITY, l0 = 0.f, l1 = 0.f;

#pragma unroll 1
    for (int jb = jb_lo; jb < jb_hi; jb++) {
        const int bi = (jb - jb_lo) & 1;
        __syncthreads();
        if (jb + 1 < jb_hi) {
            kv_load(jb + 1, bi ^ 1);
            cp_wait<1>();
        } else {
            cp_wait<0>();
        }
        __syncthreads();

        const uint32_t (*Ks)[PAD] = (const uint32_t(*)[PAD])(smem + bi * KVBUF);
        const uint32_t (*Vs)[PAD] = (const uint32_t(*)[PAD])(smem + bi * KVBUF + 64 * PAD);

        float s[8][4];
#pragma unroll
        for (int nb = 0; nb < 8; nb++) {
            s[nb][0] = s[nb][1] = s[nb][2] = s[nb][3] = 0.f;
#pragma unroll
            for (int kk = 0; kk < 8; kk++) {
                uint32_t b0 = Ks[8 * nb + g][8 * kk + c];
                uint32_t b1 = Ks[8 * nb + g][8 * kk + c + 4];
                mma_tf32(s[nb][0], s[nb][1], s[nb][2], s[nb][3],
                         qf[kk][0], qf[kk][1], qf[kk][2], qf[kk][3], b0, b1);
            }
        }

        if (jb >= n_tiles - 2) {
            const int row0g = qb * BM + 16 * w + g;
            const int col0g = jb * BN + 2 * c;
#pragma unroll
            for (int nb = 0; nb < 8; nb++) {
                int cg = col0g + 8 * nb;
                if (cg     > row0g)     s[nb][0] = -INFINITY;
                if (cg + 1 > row0g)     s[nb][1] = -INFINITY;
                if (cg     > row0g + 8) s[nb][2] = -INFINITY;
                if (cg + 1 > row0g + 8) s[nb][3] = -INFINITY;
            }
        }

        float mx0 = -INFINITY, mx1 = -INFINITY;
#pragma unroll
        for (int nb = 0; nb < 8; nb++) {
            mx0 = fmaxf(mx0, fmaxf(s[nb][0], s[nb][1]));
            mx1 = fmaxf(mx1, fmaxf(s[nb][2], s[nb][3]));
        }
#pragma unroll
        for (int off = 1; off <= 2; off <<= 1) {
            mx0 = fmaxf(mx0, __shfl_xor_sync(0xffffffffu, mx0, off));
            mx1 = fmaxf(mx1, __shfl_xor_sync(0xffffffffu, mx1, off));
        }
        float mn0 = fmaxf(m0, mx0), mn1 = fmaxf(m1, mx1);
        float a0 = exp2f(m0 - mn0), a1 = exp2f(m1 - mn1);
        m0 = mn0; m1 = mn1;

        float rs0 = 0.f, rs1 = 0.f;
#pragma unroll
        for (int nb = 0; nb < 8; nb++) {
            float p0 = exp2f(s[nb][0] - m0);
            float p1 = exp2f(s[nb][1] - m0);
            float p2 = exp2f(s[nb][2] - m1);
            float p3 = exp2f(s[nb][3] - m1);
            rs0 += p0 + p1; rs1 += p2 + p3;
            Ps[16 * w + g][8 * nb + 2 * c]         = f2tf(p0);
            Ps[16 * w + g][8 * nb + 2 * c + 1]     = f2tf(p1);
            Ps[16 * w + g + 8][8 * nb + 2 * c]     = f2tf(p2);
            Ps[16 * w + g + 8][8 * nb + 2 * c + 1] = f2tf(p3);
        }
#pragma unroll
        for (int off = 1; off <= 2; off <<= 1) {
            rs0 += __shfl_xor_sync(0xffffffffu, rs0, off);
            rs1 += __shfl_xor_sync(0xffffffffu, rs1, off);
        }
        l0 = l0 * a0 + rs0;
        l1 = l1 * a1 + rs1;
#pragma unroll
        for (int nb = 0; nb < 8; nb++) {
            o[nb][0] *= a0; o[nb][1] *= a0;
            o[nb][2] *= a1; o[nb][3] *= a1;
        }
        __syncwarp();

#pragma unroll
        for (int kk = 0; kk < 8; kk++) {
            uint32_t pa0 = Ps[16 * w + g][8 * kk + c];
            uint32_t pa1 = Ps[16 * w + g + 8][8 * kk + c];
            uint32_t pa2 = Ps[16 * w + g][8 * kk + c + 4];
            uint32_t pa3 = Ps[16 * w + g + 8][8 * kk + c + 4];
#pragma unroll
            for (int nb = 0; nb < 8; nb++) {
                uint32_t b0 = Vs[8 * kk + c][8 * nb + g];
                uint32_t b1 = Vs[8 * kk + c + 4][8 * nb + g];
                mma_tf32(o[nb][0], o[nb][1], o[nb][2], o[nb][3],
                         pa0, pa1, pa2, pa3, b0, b1);
            }
        }
    }

    const int p = ((b * QB_PER_B + qb) << 2) + sp;
    float* pacc = g_pacc + (size_t)p * BM * HD;
    const int r0 = 16 * w + g;
#pragma unroll
    for (int nb = 0; nb < 8; nb++) {
        *(float2*)&pacc[(size_t)r0 * HD + 8 * nb + 2 * c]       = make_float2(o[nb][0], o[nb][1]);
        *(float2*)&pacc[(size_t)(r0 + 8) * HD + 8 * nb + 2 * c] = make_float2(o[nb][2], o[nb][3]);
    }
    if (c == 0) {
        g_pm[p * BM + r0] = m0;     g_pm[p * BM + r0 + 8] = m1;
        g_pl[p * BM + r0] = l0;     g_pl[p * BM + r0 + 8] = l1;
    }
}

// ---------------------------------------------------------------------------
// Combine split partials -> output. Grid (128, 8): block = 16 rows x 64 cols.
// One float4 out per thread; <=4 float4 in. 1024 CTAs for latency hiding.
// ---------------------------------------------------------------------------
__global__ __launch_bounds__(256) void combine_kernel(float* __restrict__ out) {
    __shared__ float wsm[4][16];
    __shared__ float linv[16];

    const int bq = blockIdx.x;                 // 0..127
    const int b = bq >> 5;
    const int qb = bq & 31;
    const int nS = qb / 8 + 1;                 // 1..4 splits
    const int yc = blockIdx.y;                 // row chunk 0..7 (16 rows each)
    const int tid = threadIdx.x;
    const int pbase = bq << 2;

    if (tid < 16) {
        int row = yc * 16 + tid;
        float M = -INFINITY;
#pragma unroll 4
        for (int s = 0; s < nS; s++)
            M = fmaxf(M, g_pm[(pbase + s) * BM + row]);
        float L = 0.f;
#pragma unroll 4
        for (int s = 0; s < nS; s++) {
            float wgt = exp2f(g_pm[(pbase + s) * BM + row] - M);
            wsm[s][tid] = wgt;
            L += g_pl[(pbase + s) * BM + row] * wgt;
        }
        linv[tid] = 1.0f / L;
    }
    __syncthreads();

    const int row_l = tid >> 4;                // 0..15
    const int c4 = (tid & 15) << 2;            // 0..60
    const int row = yc * 16 + row_l;
    const size_t off = (size_t)row * HD + c4;

    float4 sum = make_float4(0.f, 0.f, 0.f, 0.f);
#pragma unroll 4
    for (int s = 0; s < nS; s++) {
        float4 v = *(const float4*)&g_pacc[(size_t)(pbase + s) * BM * HD + off];
        float wgt = wsm[s][row_l];
        sum.x += v.x * wgt;
        sum.y += v.y * wgt;
        sum.z += v.z * wgt;
        sum.w += v.w * wgt;
    }
    float li = linv[row_l];
    sum.x *= li; sum.y *= li; sum.z *= li; sum.w *= li;

    float* og = out + ((size_t)b * TT + (size_t)qb * BM) * HD;
    *(float4*)&og[off] = sum;
}

// ---------------------------------------------------------------------------
extern "C" void kernel_launch(void* const* d_in, const int* in_sizes, int n_in,
                              void* d_out, int out_size) {
    const float* x  = (const float*)d_in[0];
    const float* Wk = (const float*)d_in[1];
    const float* Wq = (const float*)d_in[2];
    const float* Wv = (const float*)d_in[3];
    float* out = (float*)d_out;
    (void)in_sizes; (void)n_in; (void)out_size;

    const int proj_smem = (2 * XRSZ + 4 * WSZ) * (int)sizeof(uint32_t);     // 139264
    const int flash_smem = (2 * KVBUF + 128 * PAD) * (int)sizeof(uint32_t); // 104448
    cudaFuncSetAttribute(proj_kernel,
                         cudaFuncAttributeMaxDynamicSharedMemorySize, proj_smem);
    cudaFuncSetAttribute(flash_kernel,
                         cudaFuncAttributeMaxDynamicSharedMemorySize, flash_smem);

    prep_kernel<<<96, 256>>>(Wk, Wq, Wv);
    proj_kernel<<<128, 512, proj_smem>>>(x);
    flash_kernel<<<NITEMS, 256, flash_smem>>>();
    combine_kernel<<<dim3(128, 8), 256>>>(out);
}

// round 9
// speedup vs baseline: 1.8775x; 1.1057x over previous
#include <cuda_runtime.h>
#include <math.h>
#include <stdint.h>

#define BB 4
#define TT 4096
#define CC 512
#define HD 64

#define BM 128           // q-tile rows per flash CTA
#define BN 64            // kv-tile rows
#define SPLIT 16         // max KV tiles per work item
#define QB_PER_B 32      // TT / BM
#define NITEMS_PER_B 80
#define NITEMS (BB * NITEMS_PER_B)   // 320
#define PAD 72           // flash smem row stride (u32), conflict-free LDS.64

// q/k stored head-PERMUTED tf32 bits (q pre-scaled by C^-0.5 * log2e).
// v stored per-64-token-tile TRANSPOSED [head][perm(tok)] tf32 bits.
__device__ uint32_t g_q[BB * TT * HD];
__device__ uint32_t g_k[BB * TT * HD];
__device__ uint32_t g_v[BB * TT * HD];

// pre-split W (hi/lo tf32 bits): [512 k][192 cols = Wk|Wq|Wv]
__device__ uint32_t g_wh[CC * 192];
__device__ uint32_t g_wl[CC * 192];

// split-KV partials
__device__ float g_pacc[BB * QB_PER_B * 4 * BM * HD];
__device__ float g_pm[BB * QB_PER_B * 4 * BM];
__device__ float g_pl[BB * QB_PER_B * 4 * BM];

// pair-permutation: maps j=8kk+c+4t -> 8kk+2c+t so (c, c+4) words are adjacent
__device__ __forceinline__ int permh(int j) {
    return (j & 0x38) | ((j & 3) << 1) | ((j >> 2) & 1);
}

__device__ __forceinline__ uint32_t f2tf(float f) {
    uint32_t u;
    asm("cvt.rna.tf32.f32 %0, %1;" : "=r"(u) : "f"(f));
    return u;
}

__device__ __forceinline__ void mma_tf32(float& d0, float& d1, float& d2, float& d3,
                                         uint32_t a0, uint32_t a1, uint32_t a2, uint32_t a3,
                                         uint32_t b0, uint32_t b1) {
    asm volatile(
        "mma.sync.aligned.m16n8k8.row.col.f32.tf32.tf32.f32 "
        "{%0,%1,%2,%3}, {%4,%5,%6,%7}, {%8,%9}, {%0,%1,%2,%3};"
        : "+f"(d0), "+f"(d1), "+f"(d2), "+f"(d3)
        : "r"(a0), "r"(a1), "r"(a2), "r"(a3), "r"(b0), "r"(b1));
}

__device__ __forceinline__ void tf_split(float v, uint32_t& hi, uint32_t& lo) {
    hi = f2tf(v);
    float hif = __uint_as_float(hi);
    lo = f2tf(v - hif);
}

__device__ __forceinline__ uint32_t smem_u32(const void* p) {
    return (uint32_t)__cvta_generic_to_shared(p);
}
__device__ __forceinline__ void cp_async16(uint32_t dst, const void* src) {
    asm volatile("cp.async.ca.shared.global [%0], [%1], 16;" :: "r"(dst), "l"(src));
}
__device__ __forceinline__ void cp_commit() {
    asm volatile("cp.async.commit_group;");
}
template <int N>
__device__ __forceinline__ void cp_wait() {
    asm volatile("cp.async.wait_group %0;" :: "n"(N));
}

// ---------------------------------------------------------------------------
// Prep: split W (Wk|Wq|Wv -> [512][192]) into hi/lo tf32 bits.
// ---------------------------------------------------------------------------
__global__ __launch_bounds__(256) void prep_kernel(const float* __restrict__ Wk,
                                                   const float* __restrict__ Wq,
                                                   const float* __restrict__ Wv) {
    int idx = blockIdx.x * 256 + threadIdx.x;       // float4 index, < 512*48
    if (idx >= CC * 48) return;
    int k = idx / 48;
    int c4 = (idx % 48) << 2;                       // 0..188
    const float* src;
    if (c4 < 64)       src = Wk + (size_t)k * HD + c4;
    else if (c4 < 128) src = Wq + (size_t)k * HD + (c4 - 64);
    else               src = Wv + (size_t)k * HD + (c4 - 128);
    float4 v = *(const float4*)src;
    uint4 uh, ul;
    tf_split(v.x, uh.x, ul.x);
    tf_split(v.y, uh.y, ul.y);
    tf_split(v.z, uh.z, ul.z);
    tf_split(v.w, uh.w, ul.w);
    *(uint4*)&g_wh[k * 192 + c4] = uh;
    *(uint4*)&g_wl[k * 192 + c4] = ul;
}

// ---------------------------------------------------------------------------
// Fused projection GEMM (3xTF32): [16384x512] @ [512x192]
// ---------------------------------------------------------------------------
#define KC 32
#define PXS 36                // x raw row stride
#define PWS 200               // W hi/lo row stride
#define XRSZ (128 * PXS)      // 4608
#define WSZ (KC * PWS)        // 6400

__global__ __launch_bounds__(512, 1) void proj_kernel(const float* __restrict__ x) {
    extern __shared__ uint32_t psm[];
    uint32_t* xrb[2] = { psm, psm + XRSZ };
    uint32_t* whb[2] = { psm + 2 * XRSZ, psm + 2 * XRSZ + WSZ };
    uint32_t* wlb[2] = { psm + 2 * XRSZ + 2 * WSZ, psm + 2 * XRSZ + 3 * WSZ };

    const int row0 = blockIdx.x * 128;
    const int tid = threadIdx.x;
    const int w = tid >> 5;
    const int lane = tid & 31;
    const int g = lane >> 2;
    const int c = lane & 3;
    const int wr = (w & 3) * 32;      // warp row base (0,32,64,96)
    const int wc = (w >> 2) * 48;     // warp col base (0,48,96,144)

    auto load_chunk = [&](int ch, int bi) {
#pragma unroll
        for (int it = 0; it < 2; it++) {
            int f = tid + it * 512;
            int r = f >> 3, c4 = (f & 7) << 2;
            cp_async16(smem_u32(&xrb[bi][r * PXS + c4]),
                       &x[(size_t)(row0 + r) * CC + ch * KC + c4]);
        }
#pragma unroll
        for (int it = 0; it < 6; it++) {
            int f = tid + it * 512;
            if (f < 1536) {
                int r = f / 48, c4 = (f % 48) << 2;
                cp_async16(smem_u32(&whb[bi][r * PWS + c4]),
                           &g_wh[(size_t)(ch * KC + r) * 192 + c4]);
            } else {
                int f2 = f - 1536;
                int r = f2 / 48, c4 = (f2 % 48) << 2;
                cp_async16(smem_u32(&wlb[bi][r * PWS + c4]),
                           &g_wl[(size_t)(ch * KC + r) * 192 + c4]);
            }
        }
        cp_commit();
    };

    float acc[2][6][4];
#pragma unroll
    for (int mt = 0; mt < 2; mt++)
#pragma unroll
        for (int nb = 0; nb < 6; nb++)
#pragma unroll
            for (int i = 0; i < 4; i++) acc[mt][nb][i] = 0.f;

    load_chunk(0, 0);

#pragma unroll 1
    for (int ch = 0; ch < CC / KC; ch++) {
        const int bi = ch & 1;
        __syncthreads();
        if (ch + 1 < CC / KC) {
            load_chunk(ch + 1, bi ^ 1);
            cp_wait<1>();
        } else {
            cp_wait<0>();
        }
        __syncthreads();

        const uint32_t* xr = xrb[bi];
        const uint32_t* wh = whb[bi];
        const uint32_t* wl = wlb[bi];
#pragma unroll
        for (int kk = 0; kk < KC / 8; kk++) {
            uint32_t ah[2][4], al[2][4];
#pragma unroll
            for (int mt = 0; mt < 2; mt++) {
                int r = wr + 16 * mt;
                float v0 = __uint_as_float(xr[(r + g) * PXS + 8 * kk + c]);
                float v1 = __uint_as_float(xr[(r + g + 8) * PXS + 8 * kk + c]);
                float v2 = __uint_as_float(xr[(r + g) * PXS + 8 * kk + c + 4]);
                float v3 = __uint_as_float(xr[(r + g + 8) * PXS + 8 * kk + c + 4]);
                tf_split(v0, ah[mt][0], al[mt][0]);
                tf_split(v1, ah[mt][1], al[mt][1]);
                tf_split(v2, ah[mt][2], al[mt][2]);
                tf_split(v3, ah[mt][3], al[mt][3]);
            }
#pragma unroll
            for (int nb = 0; nb < 6; nb++) {
                int bcol = wc + 8 * nb + g;
                uint32_t bh0 = wh[(8 * kk + c) * PWS + bcol];
                uint32_t bh1 = wh[(8 * kk + c + 4) * PWS + bcol];
                uint32_t bl0 = wl[(8 * kk + c) * PWS + bcol];
                uint32_t bl1 = wl[(8 * kk + c + 4) * PWS + bcol];
#pragma unroll
                for (int mt = 0; mt < 2; mt++) {
                    mma_tf32(acc[mt][nb][0], acc[mt][nb][1], acc[mt][nb][2], acc[mt][nb][3],
                             ah[mt][0], ah[mt][1], ah[mt][2], ah[mt][3], bh0, bh1);
                    mma_tf32(acc[mt][nb][0], acc[mt][nb][1], acc[mt][nb][2], acc[mt][nb][3],
                             ah[mt][0], ah[mt][1], ah[mt][2], ah[mt][3], bl0, bl1);
                    mma_tf32(acc[mt][nb][0], acc[mt][nb][1], acc[mt][nb][2], acc[mt][nb][3],
                             al[mt][0], al[mt][1], al[mt][2], al[mt][3], bh0, bh1);
                }
            }
        }
    }

    // ---- epilogue: permuted/transposed tf32 stores ----
    const float qscale = rsqrtf((float)CC) * 1.44269504088896341f;
#pragma unroll
    for (int mt = 0; mt < 2; mt++) {
#pragma unroll
        for (int nb = 0; nb < 6; nb++) {
            int colg = wc + 8 * nb + 2 * c;
            int rg0 = row0 + wr + 16 * mt + g;
            int rg1 = rg0 + 8;
            float v0 = acc[mt][nb][0], v1 = acc[mt][nb][1];
            float v2 = acc[mt][nb][2], v3 = acc[mt][nb][3];
            if (colg < 64) {                  // K: head-permuted, token-major
                int p0 = permh(colg), p1 = permh(colg + 1);
                g_k[(size_t)rg0 * HD + p0] = f2tf(v0);
                g_k[(size_t)rg0 * HD + p1] = f2tf(v1);
                g_k[(size_t)rg1 * HD + p0] = f2tf(v2);
                g_k[(size_t)rg1 * HD + p1] = f2tf(v3);
            } else if (colg < 128) {          // Q: head-permuted, scaled
                int h = colg - 64;
                int p0 = permh(h), p1 = permh(h + 1);
                g_q[(size_t)rg0 * HD + p0] = f2tf(v0 * qscale);
                g_q[(size_t)rg0 * HD + p1] = f2tf(v1 * qscale);
                g_q[(size_t)rg1 * HD + p0] = f2tf(v2 * qscale);
                g_q[(size_t)rg1 * HD + p1] = f2tf(v3 * qscale);
            } else {                          // V: per-tile transposed [head][perm(tok)]
                int h0 = colg - 128;
                int tile = rg0 >> 6;          // rg1 in same tile (see layout proof)
                int pt0 = permh(rg0 & 63);
                int pt1 = permh(rg1 & 63);
                size_t base = (size_t)tile * 4096;
                g_v[base + (size_t)h0 * 64 + pt0]       = f2tf(v0);
                g_v[base + (size_t)(h0 + 1) * 64 + pt0] = f2tf(v1);
                g_v[base + (size_t)h0 * 64 + pt1]       = f2tf(v2);
                g_v[base + (size_t)(h0 + 1) * 64 + pt1] = f2tf(v3);
            }
        }
    }
}

// ---------------------------------------------------------------------------
// Flash attention, tf32 mma, split-KV, cp.async double-buffered K/V.
// All B-fragments are single LDS.64 thanks to permuted storage.
// ---------------------------------------------------------------------------
#define KVBUF (2 * 64 * PAD)

__global__ __launch_bounds__(256, 2) void flash_kernel() {
    extern __shared__ uint32_t smem[];
    uint32_t (*Ps)[PAD] = (uint32_t(*)[PAD])(smem + 2 * KVBUF);

    const int rr = NITEMS - 1 - blockIdx.x;
    const int b = rr / NITEMS_PER_B;
    const int r = rr - b * NITEMS_PER_B;
    int qb, sp;
    if (r < 8)       { qb = r;                 sp = 0; }
    else if (r < 24) { qb = 8 + (r - 8) / 2;   sp = (r - 8) & 1; }
    else if (r < 48) { qb = 16 + (r - 24) / 3; sp = (r - 24) % 3; }
    else             { qb = 24 + (r - 48) / 4; sp = (r - 48) & 3; }

    const int n_tiles = 2 * qb + 2;
    const int jb_lo = sp * SPLIT;
    const int jb_hi = min(jb_lo + SPLIT, n_tiles);

    const int tid = threadIdx.x;
    const int w = tid >> 5;
    const int lane = tid & 31;
    const int g = lane >> 2;
    const int c = lane & 3;

    auto kv_load = [&](int jb, int bi) {
        const uint32_t* Kg = g_k + ((size_t)b * TT + (size_t)jb * BN) * HD;
        const uint32_t* Vg = g_v + ((size_t)b * TT + (size_t)jb * BN) * HD; // = tile*4096
        uint32_t* Kd = smem + bi * KVBUF;
        uint32_t* Vd = Kd + 64 * PAD;
#pragma unroll
        for (int it = 0; it < 4; it++) {
            int f = tid + it * 256;
            int row = f >> 4, c4 = (f & 15) << 2;
            cp_async16(smem_u32(&Kd[row * PAD + c4]), &Kg[(size_t)row * HD + c4]);
            cp_async16(smem_u32(&Vd[row * PAD + c4]), &Vg[(size_t)row * HD + c4]);
        }
        cp_commit();
    };

    const uint32_t* Qg = g_q + ((size_t)b * TT + (size_t)qb * BM) * HD;
#pragma unroll
    for (int it = 0; it < 8; it++) {
        int f = tid + it * 256;
        int row = f >> 4, c4 = (f & 15) << 2;
        cp_async16(smem_u32(&Ps[row][c4]), &Qg[(size_t)row * HD + c4]);
    }
    cp_commit();
    kv_load(jb_lo, 0);
    cp_wait<1>();           // Q ready
    __syncthreads();

    uint32_t qf[8][4];
#pragma unroll
    for (int kk = 0; kk < 8; kk++) {
        uint2 uq0 = *(const uint2*)&Ps[16 * w + g][8 * kk + 2 * c];
        uint2 uq1 = *(const uint2*)&Ps[16 * w + g + 8][8 * kk + 2 * c];
        qf[kk][0] = uq0.x; qf[kk][2] = uq0.y;
        qf[kk][1] = uq1.x; qf[kk][3] = uq1.y;
    }

    float o[8][4];
#pragma unroll
    for (int nb = 0; nb < 8; nb++)
#pragma unroll
        for (int i = 0; i < 4; i++) o[nb][i] = 0.f;
    float m0 = -INFINITY, m1 = -INFINITY, l0 = 0.f, l1 = 0.f;

#pragma unroll 1
    for (int jb = jb_lo; jb < jb_hi; jb++) {
        const int bi = (jb - jb_lo) & 1;
        __syncthreads();
        if (jb + 1 < jb_hi) {
            kv_load(jb + 1, bi ^ 1);
            cp_wait<1>();
        } else {
            cp_wait<0>();
        }
        __syncthreads();

        const uint32_t (*Ks)[PAD] = (const uint32_t(*)[PAD])(smem + bi * KVBUF);
        const uint32_t (*Vs)[PAD] = (const uint32_t(*)[PAD])(smem + bi * KVBUF + 64 * PAD);

        // ---- S = Q K^T ----
        float s[8][4];
#pragma unroll
        for (int nb = 0; nb < 8; nb++) {
            s[nb][0] = s[nb][1] = s[nb][2] = s[nb][3] = 0.f;
#pragma unroll
            for (int kk = 0; kk < 8; kk++) {
                uint2 ub = *(const uint2*)&Ks[8 * nb + g][8 * kk + 2 * c];
                mma_tf32(s[nb][0], s[nb][1], s[nb][2], s[nb][3],
                         qf[kk][0], qf[kk][1], qf[kk][2], qf[kk][3], ub.x, ub.y);
            }
        }

        if (jb >= n_tiles - 2) {
            const int row0g = qb * BM + 16 * w + g;
            const int col0g = jb * BN + 2 * c;
#pragma unroll
            for (int nb = 0; nb < 8; nb++) {
                int cg = col0g + 8 * nb;
                if (cg     > row0g)     s[nb][0] = -INFINITY;
                if (cg + 1 > row0g)     s[nb][1] = -INFINITY;
                if (cg     > row0g + 8) s[nb][2] = -INFINITY;
                if (cg + 1 > row0g + 8) s[nb][3] = -INFINITY;
            }
        }

        // ---- online softmax (base-2) ----
        float mx0 = -INFINITY, mx1 = -INFINITY;
#pragma unroll
        for (int nb = 0; nb < 8; nb++) {
            mx0 = fmaxf(mx0, fmaxf(s[nb][0], s[nb][1]));
            mx1 = fmaxf(mx1, fmaxf(s[nb][2], s[nb][3]));
        }
#pragma unroll
        for (int off = 1; off <= 2; off <<= 1) {
            mx0 = fmaxf(mx0, __shfl_xor_sync(0xffffffffu, mx0, off));
            mx1 = fmaxf(mx1, __shfl_xor_sync(0xffffffffu, mx1, off));
        }
        float mn0 = fmaxf(m0, mx0), mn1 = fmaxf(m1, mx1);
        float a0 = exp2f(m0 - mn0), a1 = exp2f(m1 - mn1);
        m0 = mn0; m1 = mn1;

        float rs0 = 0.f, rs1 = 0.f;
#pragma unroll
        for (int nb = 0; nb < 8; nb++) {
            float p0 = exp2f(s[nb][0] - m0);
            float p1 = exp2f(s[nb][1] - m0);
            float p2 = exp2f(s[nb][2] - m1);
            float p3 = exp2f(s[nb][3] - m1);
            rs0 += p0 + p1; rs1 += p2 + p3;
            *(uint2*)&Ps[16 * w + g][8 * nb + 2 * c]     = make_uint2(f2tf(p0), f2tf(p1));
            *(uint2*)&Ps[16 * w + g + 8][8 * nb + 2 * c] = make_uint2(f2tf(p2), f2tf(p3));
        }
#pragma unroll
        for (int off = 1; off <= 2; off <<= 1) {
            rs0 += __shfl_xor_sync(0xffffffffu, rs0, off);
            rs1 += __shfl_xor_sync(0xffffffffu, rs1, off);
        }
        l0 = l0 * a0 + rs0;
        l1 = l1 * a1 + rs1;
#pragma unroll
        for (int nb = 0; nb < 8; nb++) {
            o[nb][0] *= a0; o[nb][1] *= a0;
            o[nb][2] *= a1; o[nb][3] *= a1;
        }
        __syncwarp();

        // ---- O += P V ----
#pragma unroll
        for (int kk = 0; kk < 8; kk++) {
            uint32_t pa0 = Ps[16 * w + g][8 * kk + c];
            uint32_t pa1 = Ps[16 * w + g + 8][8 * kk + c];
            uint32_t pa2 = Ps[16 * w + g][8 * kk + c + 4];
            uint32_t pa3 = Ps[16 * w + g + 8][8 * kk + c + 4];
#pragma unroll
            for (int nb = 0; nb < 8; nb++) {
                uint2 uv = *(const uint2*)&Vs[8 * nb + g][8 * kk + 2 * c];
                mma_tf32(o[nb][0], o[nb][1], o[nb][2], o[nb][3],
                         pa0, pa1, pa2, pa3, uv.x, uv.y);
            }
        }
    }

    const int p = ((b * QB_PER_B + qb) << 2) + sp;
    float* pacc = g_pacc + (size_t)p * BM * HD;
    const int r0 = 16 * w + g;
#pragma unroll
    for (int nb = 0; nb < 8; nb++) {
        *(float2*)&pacc[(size_t)r0 * HD + 8 * nb + 2 * c]       = make_float2(o[nb][0], o[nb][1]);
        *(float2*)&pacc[(size_t)(r0 + 8) * HD + 8 * nb + 2 * c] = make_float2(o[nb][2], o[nb][3]);
    }
    if (c == 0) {
        g_pm[p * BM + r0] = m0;     g_pm[p * BM + r0 + 8] = m1;
        g_pl[p * BM + r0] = l0;     g_pl[p * BM + r0 + 8] = l1;
    }
}

// ---------------------------------------------------------------------------
// Combine split partials -> output. Grid (128, 8): block = 16 rows x 64 cols.
// ---------------------------------------------------------------------------
__global__ __launch_bounds__(256) void combine_kernel(float* __restrict__ out) {
    __shared__ float wsm[4][16];
    __shared__ float linv[16];

    const int bq = blockIdx.x;                 // 0..127
    const int b = bq >> 5;
    const int qb = bq & 31;
    const int nS = qb / 8 + 1;                 // 1..4 splits
    const int yc = blockIdx.y;                 // row chunk 0..7 (16 rows each)
    const int tid = threadIdx.x;
    const int pbase = bq << 2;

    if (tid < 16) {
        int row = yc * 16 + tid;
        float M = -INFINITY;
#pragma unroll 4
        for (int s = 0; s < nS; s++)
            M = fmaxf(M, g_pm[(pbase + s) * BM + row]);
        float L = 0.f;
#pragma unroll 4
        for (int s = 0; s < nS; s++) {
            float wgt = exp2f(g_pm[(pbase + s) * BM + row] - M);
            wsm[s][tid] = wgt;
            L += g_pl[(pbase + s) * BM + row] * wgt;
        }
        linv[tid] = 1.0f / L;
    }
    __syncthreads();

    const int row_l = tid >> 4;                // 0..15
    const int c4 = (tid & 15) << 2;            // 0..60
    const int row = yc * 16 + row_l;
    const size_t off = (size_t)row * HD + c4;

    float4 sum = make_float4(0.f, 0.f, 0.f, 0.f);
#pragma unroll 4
    for (int s = 0; s < nS; s++) {
        float4 v = *(const float4*)&g_pacc[(size_t)(pbase + s) * BM * HD + off];
        float wgt = wsm[s][row_l];
        sum.x += v.x * wgt;
        sum.y += v.y * wgt;
        sum.z += v.z * wgt;
        sum.w += v.w * wgt;
    }
    float li = linv[row_l];
    sum.x *= li; sum.y *= li; sum.z *= li; sum.w *= li;

    float* og = out + ((size_t)b * TT + (size_t)qb * BM) * HD;
    *(float4*)&og[off] = sum;
}

// ---------------------------------------------------------------------------
extern "C" void kernel_launch(void* const* d_in, const int* in_sizes, int n_in,
                              void* d_out, int out_size) {
    const float* x  = (const float*)d_in[0];
    const float* Wk = (const float*)d_in[1];
    const float* Wq = (const float*)d_in[2];
    const float* Wv = (const float*)d_in[3];
    float* out = (float*)d_out;
    (void)in_sizes; (void)n_in; (void)out_size;

    const int proj_smem = (2 * XRSZ + 4 * WSZ) * (int)sizeof(uint32_t);     // 139264
    const int flash_smem = (2 * KVBUF + 128 * PAD) * (int)sizeof(uint32_t); // 110592
    cudaFuncSetAttribute(proj_kernel,
                         cudaFuncAttributeMaxDynamicSharedMemorySize, proj_smem);
    cudaFuncSetAttribute(flash_kernel,
                         cudaFuncAttributeMaxDynamicSharedMemorySize, flash_smem);

    prep_kernel<<<96, 256>>>(Wk, Wq, Wv);
    proj_kernel<<<128, 512, proj_smem>>>(x);
    flash_kernel<<<NITEMS, 256, flash_smem>>>();
    combine_kernel<<<dim3(128, 8), 256>>>(out);
}

// round 10
// speedup vs baseline: 1.9692x; 1.0488x over previous
#include <cuda_runtime.h>
#include <math.h>
#include <stdint.h>

#define BB 4
#define TT 4096
#define CC 512
#define HD 64

#define BM 128           // q-tile rows per flash CTA
#define BN 64            // kv-tile rows
#define SPLIT 16         // max KV tiles per work item
#define QB_PER_B 32      // TT / BM
#define NITEMS_PER_B 80
#define NITEMS (BB * NITEMS_PER_B)   // 320
#define PAD 72           // flash smem row stride (u32), conflict-free LDS.64

// q/k stored head-PERMUTED tf32 bits (q pre-scaled by C^-0.5 * log2e).
// v stored per-64-token-tile TRANSPOSED [head][tok] tf32 bits (natural order).
__device__ uint32_t g_q[BB * TT * HD];
__device__ uint32_t g_k[BB * TT * HD];
__device__ uint32_t g_v[BB * TT * HD];

// pre-split W (hi/lo tf32 bits): [512 k][192 cols = Wk|Wq|Wv]
__device__ uint32_t g_wh[CC * 192];
__device__ uint32_t g_wl[CC * 192];

// split-KV partials
__device__ float g_pacc[BB * QB_PER_B * 4 * BM * HD];
__device__ float g_pm[BB * QB_PER_B * 4 * BM];
__device__ float g_pl[BB * QB_PER_B * 4 * BM];

// pair-permutation: maps j=8kk+c+4t -> 8kk+2c+t so (c, c+4) words are adjacent
__device__ __forceinline__ int permh(int j) {
    return (j & 0x38) | ((j & 3) << 1) | ((j >> 2) & 1);
}

__device__ __forceinline__ uint32_t f2tf(float f) {
    uint32_t u;
    asm("cvt.rna.tf32.f32 %0, %1;" : "=r"(u) : "f"(f));
    return u;
}

__device__ __forceinline__ void mma_tf32(float& d0, float& d1, float& d2, float& d3,
                                         uint32_t a0, uint32_t a1, uint32_t a2, uint32_t a3,
                                         uint32_t b0, uint32_t b1) {
    asm volatile(
        "mma.sync.aligned.m16n8k8.row.col.f32.tf32.tf32.f32 "
        "{%0,%1,%2,%3}, {%4,%5,%6,%7}, {%8,%9}, {%0,%1,%2,%3};"
        : "+f"(d0), "+f"(d1), "+f"(d2), "+f"(d3)
        : "r"(a0), "r"(a1), "r"(a2), "r"(a3), "r"(b0), "r"(b1));
}

__device__ __forceinline__ void tf_split(float v, uint32_t& hi, uint32_t& lo) {
    hi = f2tf(v);
    float hif = __uint_as_float(hi);
    lo = f2tf(v - hif);
}

__device__ __forceinline__ uint32_t smem_u32(const void* p) {
    return (uint32_t)__cvta_generic_to_shared(p);
}
__device__ __forceinline__ void cp_async16(uint32_t dst, const void* src) {
    asm volatile("cp.async.ca.shared.global [%0], [%1], 16;" :: "r"(dst), "l"(src));
}
__device__ __forceinline__ void cp_commit() {
    asm volatile("cp.async.commit_group;");
}
template <int N>
__device__ __forceinline__ void cp_wait() {
    asm volatile("cp.async.wait_group %0;" :: "n"(N));
}

// ---------------------------------------------------------------------------
// Prep: split W (Wk|Wq|Wv -> [512][192]) into hi/lo tf32 bits.
// ---------------------------------------------------------------------------
__global__ __launch_bounds__(256) void prep_kernel(const float* __restrict__ Wk,
                                                   const float* __restrict__ Wq,
                                                   const float* __restrict__ Wv) {
    int idx = blockIdx.x * 256 + threadIdx.x;       // float4 index, < 512*48
    if (idx >= CC * 48) return;
    int k = idx / 48;
    int c4 = (idx % 48) << 2;                       // 0..188
    const float* src;
    if (c4 < 64)       src = Wk + (size_t)k * HD + c4;
    else if (c4 < 128) src = Wq + (size_t)k * HD + (c4 - 64);
    else               src = Wv + (size_t)k * HD + (c4 - 128);
    float4 v = *(const float4*)src;
    uint4 uh, ul;
    tf_split(v.x, uh.x, ul.x);
    tf_split(v.y, uh.y, ul.y);
    tf_split(v.z, uh.z, ul.z);
    tf_split(v.w, uh.w, ul.w);
    *(uint4*)&g_wh[k * 192 + c4] = uh;
    *(uint4*)&g_wl[k * 192 + c4] = ul;
}

// ---------------------------------------------------------------------------
// Fused projection GEMM (3xTF32): [16384x512] @ [512x192]
// ---------------------------------------------------------------------------
#define KC 32
#define PXS 36                // x raw row stride
#define PWS 200               // W hi/lo row stride
#define XRSZ (128 * PXS)      // 4608
#define WSZ (KC * PWS)        // 6400

__global__ __launch_bounds__(512, 1) void proj_kernel(const float* __restrict__ x) {
    extern __shared__ uint32_t psm[];
    uint32_t* xrb[2] = { psm, psm + XRSZ };
    uint32_t* whb[2] = { psm + 2 * XRSZ, psm + 2 * XRSZ + WSZ };
    uint32_t* wlb[2] = { psm + 2 * XRSZ + 2 * WSZ, psm + 2 * XRSZ + 3 * WSZ };

    const int row0 = blockIdx.x * 128;
    const int tid = threadIdx.x;
    const int w = tid >> 5;
    const int lane = tid & 31;
    const int g = lane >> 2;
    const int c = lane & 3;
    const int wr = (w & 3) * 32;      // warp row base (0,32,64,96)
    const int wc = (w >> 2) * 48;     // warp col base (0,48,96,144)

    auto load_chunk = [&](int ch, int bi) {
#pragma unroll
        for (int it = 0; it < 2; it++) {
            int f = tid + it * 512;
            int r = f >> 3, c4 = (f & 7) << 2;
            cp_async16(smem_u32(&xrb[bi][r * PXS + c4]),
                       &x[(size_t)(row0 + r) * CC + ch * KC + c4]);
        }
#pragma unroll
        for (int it = 0; it < 6; it++) {
            int f = tid + it * 512;
            if (f < 1536) {
                int r = f / 48, c4 = (f % 48) << 2;
                cp_async16(smem_u32(&whb[bi][r * PWS + c4]),
                           &g_wh[(size_t)(ch * KC + r) * 192 + c4]);
            } else {
                int f2 = f - 1536;
                int r = f2 / 48, c4 = (f2 % 48) << 2;
                cp_async16(smem_u32(&wlb[bi][r * PWS + c4]),
                           &g_wl[(size_t)(ch * KC + r) * 192 + c4]);
            }
        }
        cp_commit();
    };

    float acc[2][6][4];
#pragma unroll
    for (int mt = 0; mt < 2; mt++)
#pragma unroll
        for (int nb = 0; nb < 6; nb++)
#pragma unroll
            for (int i = 0; i < 4; i++) acc[mt][nb][i] = 0.f;

    load_chunk(0, 0);

#pragma unroll 1
    for (int ch = 0; ch < CC / KC; ch++) {
        const int bi = ch & 1;
        __syncthreads();
        if (ch + 1 < CC / KC) {
            load_chunk(ch + 1, bi ^ 1);
            cp_wait<1>();
        } else {
            cp_wait<0>();
        }
        __syncthreads();

        const uint32_t* xr = xrb[bi];
        const uint32_t* wh = whb[bi];
        const uint32_t* wl = wlb[bi];
#pragma unroll
        for (int kk = 0; kk < KC / 8; kk++) {
            uint32_t ah[2][4], al[2][4];
#pragma unroll
            for (int mt = 0; mt < 2; mt++) {
                int r = wr + 16 * mt;
                float v0 = __uint_as_float(xr[(r + g) * PXS + 8 * kk + c]);
                float v1 = __uint_as_float(xr[(r + g + 8) * PXS + 8 * kk + c]);
                float v2 = __uint_as_float(xr[(r + g) * PXS + 8 * kk + c + 4]);
                float v3 = __uint_as_float(xr[(r + g + 8) * PXS + 8 * kk + c + 4]);
                tf_split(v0, ah[mt][0], al[mt][0]);
                tf_split(v1, ah[mt][1], al[mt][1]);
                tf_split(v2, ah[mt][2], al[mt][2]);
                tf_split(v3, ah[mt][3], al[mt][3]);
            }
#pragma unroll
            for (int nb = 0; nb < 6; nb++) {
                int bcol = wc + 8 * nb + g;
                uint32_t bh0 = wh[(8 * kk + c) * PWS + bcol];
                uint32_t bh1 = wh[(8 * kk + c + 4) * PWS + bcol];
                uint32_t bl0 = wl[(8 * kk + c) * PWS + bcol];
                uint32_t bl1 = wl[(8 * kk + c + 4) * PWS + bcol];
#pragma unroll
                for (int mt = 0; mt < 2; mt++) {
                    mma_tf32(acc[mt][nb][0], acc[mt][nb][1], acc[mt][nb][2], acc[mt][nb][3],
                             ah[mt][0], ah[mt][1], ah[mt][2], ah[mt][3], bh0, bh1);
                    mma_tf32(acc[mt][nb][0], acc[mt][nb][1], acc[mt][nb][2], acc[mt][nb][3],
                             ah[mt][0], ah[mt][1], ah[mt][2], ah[mt][3], bl0, bl1);
                    mma_tf32(acc[mt][nb][0], acc[mt][nb][1], acc[mt][nb][2], acc[mt][nb][3],
                             al[mt][0], al[mt][1], al[mt][2], al[mt][3], bh0, bh1);
                }
            }
        }
    }

    // ---- epilogue: permuted (q/k) and tile-transposed (v) tf32 stores ----
    const float qscale = rsqrtf((float)CC) * 1.44269504088896341f;
#pragma unroll
    for (int mt = 0; mt < 2; mt++) {
#pragma unroll
        for (int nb = 0; nb < 6; nb++) {
            int colg = wc + 8 * nb + 2 * c;
            int rg0 = row0 + wr + 16 * mt + g;
            int rg1 = rg0 + 8;
            float v0 = acc[mt][nb][0], v1 = acc[mt][nb][1];
            float v2 = acc[mt][nb][2], v3 = acc[mt][nb][3];
            if (colg < 64) {                  // K: head-permuted, token-major
                int p0 = permh(colg), p1 = permh(colg + 1);
                g_k[(size_t)rg0 * HD + p0] = f2tf(v0);
                g_k[(size_t)rg0 * HD + p1] = f2tf(v1);
                g_k[(size_t)rg1 * HD + p0] = f2tf(v2);
                g_k[(size_t)rg1 * HD + p1] = f2tf(v3);
            } else if (colg < 128) {          // Q: head-permuted, scaled
                int h = colg - 64;
                int p0 = permh(h), p1 = permh(h + 1);
                g_q[(size_t)rg0 * HD + p0] = f2tf(v0 * qscale);
                g_q[(size_t)rg0 * HD + p1] = f2tf(v1 * qscale);
                g_q[(size_t)rg1 * HD + p0] = f2tf(v2 * qscale);
                g_q[(size_t)rg1 * HD + p1] = f2tf(v3 * qscale);
            } else {                          // V: per-tile transposed [head][tok]
                int h0 = colg - 128;
                int tile = rg0 >> 6;          // rg1 in same tile
                int pt0 = rg0 & 63;
                int pt1 = rg1 & 63;
                size_t base = (size_t)tile * 4096;
                g_v[base + (size_t)h0 * 64 + pt0]       = f2tf(v0);
                g_v[base + (size_t)(h0 + 1) * 64 + pt0] = f2tf(v1);
                g_v[base + (size_t)h0 * 64 + pt1]       = f2tf(v2);
                g_v[base + (size_t)(h0 + 1) * 64 + pt1] = f2tf(v3);
            }
        }
    }
}

// ---------------------------------------------------------------------------
// Flash attention, tf32 mma, split-KV, cp.async double-buffered K/V.
// B-fragments single LDS.64; P stays in registers (C-frag == A-frag identity
// under natural-token V storage).
// ---------------------------------------------------------------------------
#define KVBUF (2 * 64 * PAD)

__global__ __launch_bounds__(256, 2) void flash_kernel() {
    extern __shared__ uint32_t smem[];
    uint32_t (*Ps)[PAD] = (uint32_t(*)[PAD])(smem + 2 * KVBUF);  // Q staging only

    const int rr = NITEMS - 1 - blockIdx.x;
    const int b = rr / NITEMS_PER_B;
    const int r = rr - b * NITEMS_PER_B;
    int qb, sp;
    if (r < 8)       { qb = r;                 sp = 0; }
    else if (r < 24) { qb = 8 + (r - 8) / 2;   sp = (r - 8) & 1; }
    else if (r < 48) { qb = 16 + (r - 24) / 3; sp = (r - 24) % 3; }
    else             { qb = 24 + (r - 48) / 4; sp = (r - 48) & 3; }

    const int n_tiles = 2 * qb + 2;
    const int jb_lo = sp * SPLIT;
    const int jb_hi = min(jb_lo + SPLIT, n_tiles);

    const int tid = threadIdx.x;
    const int w = tid >> 5;
    const int lane = tid & 31;
    const int g = lane >> 2;
    const int c = lane & 3;

    auto kv_load = [&](int jb, int bi) {
        const uint32_t* Kg = g_k + ((size_t)b * TT + (size_t)jb * BN) * HD;
        const uint32_t* Vg = g_v + ((size_t)b * TT + (size_t)jb * BN) * HD; // = tile*4096
        uint32_t* Kd = smem + bi * KVBUF;
        uint32_t* Vd = Kd + 64 * PAD;
#pragma unroll
        for (int it = 0; it < 4; it++) {
            int f = tid + it * 256;
            int row = f >> 4, c4 = (f & 15) << 2;
            cp_async16(smem_u32(&Kd[row * PAD + c4]), &Kg[(size_t)row * HD + c4]);
            cp_async16(smem_u32(&Vd[row * PAD + c4]), &Vg[(size_t)row * HD + c4]);
        }
        cp_commit();
    };

    const uint32_t* Qg = g_q + ((size_t)b * TT + (size_t)qb * BM) * HD;
#pragma unroll
    for (int it = 0; it < 8; it++) {
        int f = tid + it * 256;
        int row = f >> 4, c4 = (f & 15) << 2;
        cp_async16(smem_u32(&Ps[row][c4]), &Qg[(size_t)row * HD + c4]);
    }
    cp_commit();
    kv_load(jb_lo, 0);
    cp_wait<1>();           // Q ready
    __syncthreads();

    uint32_t qf[8][4];
#pragma unroll
    for (int kk = 0; kk < 8; kk++) {
        uint2 uq0 = *(const uint2*)&Ps[16 * w + g][8 * kk + 2 * c];
        uint2 uq1 = *(const uint2*)&Ps[16 * w + g + 8][8 * kk + 2 * c];
        qf[kk][0] = uq0.x; qf[kk][2] = uq0.y;
        qf[kk][1] = uq1.x; qf[kk][3] = uq1.y;
    }

    float o[8][4];
#pragma unroll
    for (int nb = 0; nb < 8; nb++)
#pragma unroll
        for (int i = 0; i < 4; i++) o[nb][i] = 0.f;
    float m0 = -INFINITY, m1 = -INFINITY, l0 = 0.f, l1 = 0.f;

#pragma unroll 1
    for (int jb = jb_lo; jb < jb_hi; jb++) {
        const int bi = (jb - jb_lo) & 1;
        __syncthreads();
        if (jb + 1 < jb_hi) {
            kv_load(jb + 1, bi ^ 1);
            cp_wait<1>();
        } else {
            cp_wait<0>();
        }
        __syncthreads();

        const uint32_t (*Ks)[PAD] = (const uint32_t(*)[PAD])(smem + bi * KVBUF);
        const uint32_t (*Vs)[PAD] = (const uint32_t(*)[PAD])(smem + bi * KVBUF + 64 * PAD);

        // ---- S = Q K^T ----
        float s[8][4];
#pragma unroll
        for (int nb = 0; nb < 8; nb++) {
            s[nb][0] = s[nb][1] = s[nb][2] = s[nb][3] = 0.f;
#pragma unroll
            for (int kk = 0; kk < 8; kk++) {
                uint2 ub = *(const uint2*)&Ks[8 * nb + g][8 * kk + 2 * c];
                mma_tf32(s[nb][0], s[nb][1], s[nb][2], s[nb][3],
                         qf[kk][0], qf[kk][1], qf[kk][2], qf[kk][3], ub.x, ub.y);
            }
        }

        if (jb >= n_tiles - 2) {
            const int row0g = qb * BM + 16 * w + g;
            const int col0g = jb * BN + 2 * c;
#pragma unroll
            for (int nb = 0; nb < 8; nb++) {
                int cg = col0g + 8 * nb;
                if (cg     > row0g)     s[nb][0] = -INFINITY;
                if (cg + 1 > row0g)     s[nb][1] = -INFINITY;
                if (cg     > row0g + 8) s[nb][2] = -INFINITY;
                if (cg + 1 > row0g + 8) s[nb][3] = -INFINITY;
            }
        }

        // ---- online softmax (base-2); P kept in registers as tf32 bits ----
        float mx0 = -INFINITY, mx1 = -INFINITY;
#pragma unroll
        for (int nb = 0; nb < 8; nb++) {
            mx0 = fmaxf(mx0, fmaxf(s[nb][0], s[nb][1]));
            mx1 = fmaxf(mx1, fmaxf(s[nb][2], s[nb][3]));
        }
#pragma unroll
        for (int off = 1; off <= 2; off <<= 1) {
            mx0 = fmaxf(mx0, __shfl_xor_sync(0xffffffffu, mx0, off));
            mx1 = fmaxf(mx1, __shfl_xor_sync(0xffffffffu, mx1, off));
        }
        float mn0 = fmaxf(m0, mx0), mn1 = fmaxf(m1, mx1);
        float a0 = exp2f(m0 - mn0), a1 = exp2f(m1 - mn1);
        m0 = mn0; m1 = mn1;

        float rs0 = 0.f, rs1 = 0.f;
#pragma unroll
        for (int nb = 0; nb < 8; nb++) {
            float p0 = exp2f(s[nb][0] - m0);
            float p1 = exp2f(s[nb][1] - m0);
            float p2 = exp2f(s[nb][2] - m1);
            float p3 = exp2f(s[nb][3] - m1);
            rs0 += p0 + p1; rs1 += p2 + p3;
            s[nb][0] = __uint_as_float(f2tf(p0));
            s[nb][1] = __uint_as_float(f2tf(p1));
            s[nb][2] = __uint_as_float(f2tf(p2));
            s[nb][3] = __uint_as_float(f2tf(p3));
        }
#pragma unroll
        for (int off = 1; off <= 2; off <<= 1) {
            rs0 += __shfl_xor_sync(0xffffffffu, rs0, off);
            rs1 += __shfl_xor_sync(0xffffffffu, rs1, off);
        }
        l0 = l0 * a0 + rs0;
        l1 = l1 * a1 + rs1;
#pragma unroll
        for (int nb = 0; nb < 8; nb++) {
            o[nb][0] *= a0; o[nb][1] *= a0;
            o[nb][2] *= a1; o[nb][3] *= a1;
        }

        // ---- O += P V (P A-frags directly from registers) ----
#pragma unroll
        for (int kk = 0; kk < 8; kk++) {
            uint32_t pa0 = __float_as_uint(s[kk][0]);   // row g,   k-slot c   -> tok 8kk+2c
            uint32_t pa1 = __float_as_uint(s[kk][2]);   // row g+8, k-slot c
            uint32_t pa2 = __float_as_uint(s[kk][1]);   // row g,   k-slot c+4 -> tok 8kk+2c+1
            uint32_t pa3 = __float_as_uint(s[kk][3]);   // row g+8, k-slot c+4
#pragma unroll
            for (int nb = 0; nb < 8; nb++) {
                uint2 uv = *(const uint2*)&Vs[8 * nb + g][8 * kk + 2 * c];
                mma_tf32(o[nb][0], o[nb][1], o[nb][2], o[nb][3],
                         pa0, pa1, pa2, pa3, uv.x, uv.y);
            }
        }
    }

    const int p = ((b * QB_PER_B + qb) << 2) + sp;
    float* pacc = g_pacc + (size_t)p * BM * HD;
    const int r0 = 16 * w + g;
#pragma unroll
    for (int nb = 0; nb < 8; nb++) {
        *(float2*)&pacc[(size_t)r0 * HD + 8 * nb + 2 * c]       = make_float2(o[nb][0], o[nb][1]);
        *(float2*)&pacc[(size_t)(r0 + 8) * HD + 8 * nb + 2 * c] = make_float2(o[nb][2], o[nb][3]);
    }
    if (c == 0) {
        g_pm[p * BM + r0] = m0;     g_pm[p * BM + r0 + 8] = m1;
        g_pl[p * BM + r0] = l0;     g_pl[p * BM + r0 + 8] = l1;
    }
}

// ---------------------------------------------------------------------------
// Combine split partials -> output. Grid (128, 8): block = 16 rows x 64 cols.
// ---------------------------------------------------------------------------
__global__ __launch_bounds__(256) void combine_kernel(float* __restrict__ out) {
    __shared__ float wsm[4][16];
    __shared__ float linv[16];

    const int bq = blockIdx.x;                 // 0..127
    const int b = bq >> 5;
    const int qb = bq & 31;
    const int nS = qb / 8 + 1;                 // 1..4 splits
    const int yc = blockIdx.y;                 // row chunk 0..7 (16 rows each)
    const int tid = threadIdx.x;
    const int pbase = bq << 2;

    if (tid < 16) {
        int row = yc * 16 + tid;
        float M = -INFINITY;
#pragma unroll 4
        for (int s = 0; s < nS; s++)
            M = fmaxf(M, g_pm[(pbase + s) * BM + row]);
        float L = 0.f;
#pragma unroll 4
        for (int s = 0; s < nS; s++) {
            float wgt = exp2f(g_pm[(pbase + s) * BM + row] - M);
            wsm[s][tid] = wgt;
            L += g_pl[(pbase + s) * BM + row] * wgt;
        }
        linv[tid] = 1.0f / L;
    }
    __syncthreads();

    const int row_l = tid >> 4;                // 0..15
    const int c4 = (tid & 15) << 2;            // 0..60
    const int row = yc * 16 + row_l;
    const size_t off = (size_t)row * HD + c4;

    float4 sum = make_float4(0.f, 0.f, 0.f, 0.f);
#pragma unroll 4
    for (int s = 0; s < nS; s++) {
        float4 v = *(const float4*)&g_pacc[(size_t)(pbase + s) * BM * HD + off];
        float wgt = wsm[s][row_l];
        sum.x += v.x * wgt;
        sum.y += v.y * wgt;
        sum.z += v.z * wgt;
        sum.w += v.w * wgt;
    }
    float li = linv[row_l];
    sum.x *= li; sum.y *= li; sum.z *= li; sum.w *= li;

    float* og = out + ((size_t)b * TT + (size_t)qb * BM) * HD;
    *(float4*)&og[off] = sum;
}

// ---------------------------------------------------------------------------
extern "C" void kernel_launch(void* const* d_in, const int* in_sizes, int n_in,
                              void* d_out, int out_size) {
    const float* x  = (const float*)d_in[0];
    const float* Wk = (const float*)d_in[1];
    const float* Wq = (const float*)d_in[2];
    const float* Wv = (const float*)d_in[3];
    float* out = (float*)d_out;
    (void)in_sizes; (void)n_in; (void)out_size;

    const int proj_smem = (2 * XRSZ + 4 * WSZ) * (int)sizeof(uint32_t);     // 139264
    const int flash_smem = (2 * KVBUF + 128 * PAD) * (int)sizeof(uint32_t); // 110592
    cudaFuncSetAttribute(proj_kernel,
                         cudaFuncAttributeMaxDynamicSharedMemorySize, proj_smem);
    cudaFuncSetAttribute(flash_kernel,
                         cudaFuncAttributeMaxDynamicSharedMemorySize, flash_smem);

    prep_kernel<<<96, 256>>>(Wk, Wq, Wv);
    proj_kernel<<<128, 512, proj_smem>>>(x);
    flash_kernel<<<NITEMS, 256, flash_smem>>>();
    combine_kernel<<<dim3(128, 8), 256>>>(out);
}

// round 11
// speedup vs baseline: 2.2470x; 1.1411x over previous
#include <cuda_runtime.h>
#include <math.h>
#include <stdint.h>

#define BB 4
#define TT 4096
#define CC 512
#define HD 64

#define BM 128           // q-tile rows per flash CTA
#define BN 64            // kv-tile rows
#define SPLIT 16         // max KV tiles per work item
#define QB_PER_B 32      // TT / BM
#define NITEMS_PER_B 80
#define NITEMS (BB * NITEMS_PER_B)   // 320
#define PAD 72           // flash smem row stride (u32), conflict-free LDS.64

// q/k stored head-PERMUTED tf32 bits (q pre-scaled by C^-0.5 * log2e).
// v stored per-64-token-tile TRANSPOSED [head][tok] tf32 bits (natural order).
__device__ uint32_t g_q[BB * TT * HD];
__device__ uint32_t g_k[BB * TT * HD];
__device__ uint32_t g_v[BB * TT * HD];

// pre-split W (hi/lo tf32 bits): [512 k][192 cols = Wk|Wq|Wv]
__device__ uint32_t g_wh[CC * 192];
__device__ uint32_t g_wl[CC * 192];

// split-KV partials
__device__ float g_pacc[BB * QB_PER_B * 4 * BM * HD];
__device__ float g_pm[BB * QB_PER_B * 4 * BM];
__device__ float g_pl[BB * QB_PER_B * 4 * BM];

// pair-permutation: maps j=8kk+c+4t -> 8kk+2c+t so (c, c+4) words are adjacent
__device__ __forceinline__ int permh(int j) {
    return (j & 0x38) | ((j & 3) << 1) | ((j >> 2) & 1);
}

__device__ __forceinline__ uint32_t f2tf(float f) {
    uint32_t u;
    asm("cvt.rna.tf32.f32 %0, %1;" : "=r"(u) : "f"(f));
    return u;
}

__device__ __forceinline__ void mma_tf32(float& d0, float& d1, float& d2, float& d3,
                                         uint32_t a0, uint32_t a1, uint32_t a2, uint32_t a3,
                                         uint32_t b0, uint32_t b1) {
    asm volatile(
        "mma.sync.aligned.m16n8k8.row.col.f32.tf32.tf32.f32 "
        "{%0,%1,%2,%3}, {%4,%5,%6,%7}, {%8,%9}, {%0,%1,%2,%3};"
        : "+f"(d0), "+f"(d1), "+f"(d2), "+f"(d3)
        : "r"(a0), "r"(a1), "r"(a2), "r"(a3), "r"(b0), "r"(b1));
}

__device__ __forceinline__ void tf_split(float v, uint32_t& hi, uint32_t& lo) {
    hi = f2tf(v);
    float hif = __uint_as_float(hi);
    lo = f2tf(v - hif);
}

__device__ __forceinline__ uint32_t smem_u32(const void* p) {
    return (uint32_t)__cvta_generic_to_shared(p);
}
__device__ __forceinline__ void cp_async16(uint32_t dst, const void* src) {
    asm volatile("cp.async.ca.shared.global [%0], [%1], 16;" :: "r"(dst), "l"(src));
}
__device__ __forceinline__ void cp_commit() {
    asm volatile("cp.async.commit_group;");
}
template <int N>
__device__ __forceinline__ void cp_wait() {
    asm volatile("cp.async.wait_group %0;" :: "n"(N));
}

// ---------------------------------------------------------------------------
// Prep: split W (Wk|Wq|Wv -> [512][192]) into hi/lo tf32 bits.
// ---------------------------------------------------------------------------
__global__ __launch_bounds__(256) void prep_kernel(const float* __restrict__ Wk,
                                                   const float* __restrict__ Wq,
                                                   const float* __restrict__ Wv) {
    int idx = blockIdx.x * 256 + threadIdx.x;       // float4 index, < 512*48
    if (idx >= CC * 48) return;
    int k = idx / 48;
    int c4 = (idx % 48) << 2;                       // 0..188
    const float* src;
    if (c4 < 64)       src = Wk + (size_t)k * HD + c4;
    else if (c4 < 128) src = Wq + (size_t)k * HD + (c4 - 64);
    else               src = Wv + (size_t)k * HD + (c4 - 128);
    float4 v = *(const float4*)src;
    uint4 uh, ul;
    tf_split(v.x, uh.x, ul.x);
    tf_split(v.y, uh.y, ul.y);
    tf_split(v.z, uh.z, ul.z);
    tf_split(v.w, uh.w, ul.w);
    *(uint4*)&g_wh[k * 192 + c4] = uh;
    *(uint4*)&g_wl[k * 192 + c4] = ul;
}

// ---------------------------------------------------------------------------
// Fused projection GEMM (2xTF32: ah*bh + ah*bl, W effectively exact):
// [16384x512] @ [512x192]
// ---------------------------------------------------------------------------
#define KC 32
#define PXS 36                // x raw row stride
#define PWS 200               // W hi/lo row stride
#define XRSZ (128 * PXS)      // 4608
#define WSZ (KC * PWS)        // 6400

__global__ __launch_bounds__(512, 1) void proj_kernel(const float* __restrict__ x) {
    extern __shared__ uint32_t psm[];
    uint32_t* xrb[2] = { psm, psm + XRSZ };
    uint32_t* whb[2] = { psm + 2 * XRSZ, psm + 2 * XRSZ + WSZ };
    uint32_t* wlb[2] = { psm + 2 * XRSZ + 2 * WSZ, psm + 2 * XRSZ + 3 * WSZ };

    const int row0 = blockIdx.x * 128;
    const int tid = threadIdx.x;
    const int w = tid >> 5;
    const int lane = tid & 31;
    const int g = lane >> 2;
    const int c = lane & 3;
    const int wr = (w & 3) * 32;      // warp row base (0,32,64,96)
    const int wc = (w >> 2) * 48;     // warp col base (0,48,96,144)

    auto load_chunk = [&](int ch, int bi) {
#pragma unroll
        for (int it = 0; it < 2; it++) {
            int f = tid + it * 512;
            int r = f >> 3, c4 = (f & 7) << 2;
            cp_async16(smem_u32(&xrb[bi][r * PXS + c4]),
                       &x[(size_t)(row0 + r) * CC + ch * KC + c4]);
        }
#pragma unroll
        for (int it = 0; it < 6; it++) {
            int f = tid + it * 512;
            if (f < 1536) {
                int r = f / 48, c4 = (f % 48) << 2;
                cp_async16(smem_u32(&whb[bi][r * PWS + c4]),
                           &g_wh[(size_t)(ch * KC + r) * 192 + c4]);
            } else {
                int f2 = f - 1536;
                int r = f2 / 48, c4 = (f2 % 48) << 2;
                cp_async16(smem_u32(&wlb[bi][r * PWS + c4]),
                           &g_wl[(size_t)(ch * KC + r) * 192 + c4]);
            }
        }
        cp_commit();
    };

    float acc[2][6][4];
#pragma unroll
    for (int mt = 0; mt < 2; mt++)
#pragma unroll
        for (int nb = 0; nb < 6; nb++)
#pragma unroll
            for (int i = 0; i < 4; i++) acc[mt][nb][i] = 0.f;

    load_chunk(0, 0);

#pragma unroll 1
    for (int ch = 0; ch < CC / KC; ch++) {
        const int bi = ch & 1;
        __syncthreads();
        if (ch + 1 < CC / KC) {
            load_chunk(ch + 1, bi ^ 1);
            cp_wait<1>();
        } else {
            cp_wait<0>();
        }
        __syncthreads();

        const uint32_t* xr = xrb[bi];
        const uint32_t* wh = whb[bi];
        const uint32_t* wl = wlb[bi];
#pragma unroll
        for (int kk = 0; kk < KC / 8; kk++) {
            uint32_t ah[2][4];
#pragma unroll
            for (int mt = 0; mt < 2; mt++) {
                int r = wr + 16 * mt;
                ah[mt][0] = f2tf(__uint_as_float(xr[(r + g) * PXS + 8 * kk + c]));
                ah[mt][1] = f2tf(__uint_as_float(xr[(r + g + 8) * PXS + 8 * kk + c]));
                ah[mt][2] = f2tf(__uint_as_float(xr[(r + g) * PXS + 8 * kk + c + 4]));
                ah[mt][3] = f2tf(__uint_as_float(xr[(r + g + 8) * PXS + 8 * kk + c + 4]));
            }
#pragma unroll
            for (int nb = 0; nb < 6; nb++) {
                int bcol = wc + 8 * nb + g;
                uint32_t bh0 = wh[(8 * kk + c) * PWS + bcol];
                uint32_t bh1 = wh[(8 * kk + c + 4) * PWS + bcol];
                uint32_t bl0 = wl[(8 * kk + c) * PWS + bcol];
                uint32_t bl1 = wl[(8 * kk + c + 4) * PWS + bcol];
#pragma unroll
                for (int mt = 0; mt < 2; mt++) {
                    mma_tf32(acc[mt][nb][0], acc[mt][nb][1], acc[mt][nb][2], acc[mt][nb][3],
                             ah[mt][0], ah[mt][1], ah[mt][2], ah[mt][3], bh0, bh1);
                    mma_tf32(acc[mt][nb][0], acc[mt][nb][1], acc[mt][nb][2], acc[mt][nb][3],
                             ah[mt][0], ah[mt][1], ah[mt][2], ah[mt][3], bl0, bl1);
                }
            }
        }
    }

    // ---- epilogue: permuted (q/k) and tile-transposed (v) tf32 stores ----
    const float qscale = rsqrtf((float)CC) * 1.44269504088896341f;
#pragma unroll
    for (int mt = 0; mt < 2; mt++) {
#pragma unroll
        for (int nb = 0; nb < 6; nb++) {
            int colg = wc + 8 * nb + 2 * c;
            int rg0 = row0 + wr + 16 * mt + g;
            int rg1 = rg0 + 8;
            float v0 = acc[mt][nb][0], v1 = acc[mt][nb][1];
            float v2 = acc[mt][nb][2], v3 = acc[mt][nb][3];
            if (colg < 64) {                  // K: head-permuted, token-major
                int p0 = permh(colg), p1 = permh(colg + 1);
                g_k[(size_t)rg0 * HD + p0] = f2tf(v0);
                g_k[(size_t)rg0 * HD + p1] = f2tf(v1);
                g_k[(size_t)rg1 * HD + p0] = f2tf(v2);
                g_k[(size_t)rg1 * HD + p1] = f2tf(v3);
            } else if (colg < 128) {          // Q: head-permuted, scaled
                int h = colg - 64;
                int p0 = permh(h), p1 = permh(h + 1);
                g_q[(size_t)rg0 * HD + p0] = f2tf(v0 * qscale);
                g_q[(size_t)rg0 * HD + p1] = f2tf(v1 * qscale);
                g_q[(size_t)rg1 * HD + p0] = f2tf(v2 * qscale);
                g_q[(size_t)rg1 * HD + p1] = f2tf(v3 * qscale);
            } else {                          // V: per-tile transposed [head][tok]
                int h0 = colg - 128;
                int tile = rg0 >> 6;          // rg1 in same tile
                int pt0 = rg0 & 63;
                int pt1 = rg1 & 63;
                size_t base = (size_t)tile * 4096;
                g_v[base + (size_t)h0 * 64 + pt0]       = f2tf(v0);
                g_v[base + (size_t)(h0 + 1) * 64 + pt0] = f2tf(v1);
                g_v[base + (size_t)h0 * 64 + pt1]       = f2tf(v2);
                g_v[base + (size_t)(h0 + 1) * 64 + pt1] = f2tf(v3);
            }
        }
    }
}

// ---------------------------------------------------------------------------
// Flash attention, tf32 mma, split-KV, cp.async double-buffered K/V.
// B-fragments single LDS.64; P stays in registers.
// ---------------------------------------------------------------------------
#define KVBUF (2 * 64 * PAD)

__global__ __launch_bounds__(256, 2) void flash_kernel() {
    extern __shared__ uint32_t smem[];
    uint32_t (*Ps)[PAD] = (uint32_t(*)[PAD])(smem + 2 * KVBUF);  // Q staging only

    const int rr = NITEMS - 1 - blockIdx.x;
    const int b = rr / NITEMS_PER_B;
    const int r = rr - b * NITEMS_PER_B;
    int qb, sp;
    if (r < 8)       { qb = r;                 sp = 0; }
    else if (r < 24) { qb = 8 + (r - 8) / 2;   sp = (r - 8) & 1; }
    else if (r < 48) { qb = 16 + (r - 24) / 3; sp = (r - 24) % 3; }
    else             { qb = 24 + (r - 48) / 4; sp = (r - 48) & 3; }

    const int n_tiles = 2 * qb + 2;
    const int jb_lo = sp * SPLIT;
    const int jb_hi = min(jb_lo + SPLIT, n_tiles);

    const int tid = threadIdx.x;
    const int w = tid >> 5;
    const int lane = tid & 31;
    const int g = lane >> 2;
    const int c = lane & 3;

    auto kv_load = [&](int jb, int bi) {
        const uint32_t* Kg = g_k + ((size_t)b * TT + (size_t)jb * BN) * HD;
        const uint32_t* Vg = g_v + ((size_t)b * TT + (size_t)jb * BN) * HD; // = tile*4096
        uint32_t* Kd = smem + bi * KVBUF;
        uint32_t* Vd = Kd + 64 * PAD;
#pragma unroll
        for (int it = 0; it < 4; it++) {
            int f = tid + it * 256;
            int row = f >> 4, c4 = (f & 15) << 2;
            cp_async16(smem_u32(&Kd[row * PAD + c4]), &Kg[(size_t)row * HD + c4]);
            cp_async16(smem_u32(&Vd[row * PAD + c4]), &Vg[(size_t)row * HD + c4]);
        }
        cp_commit();
    };

    const uint32_t* Qg = g_q + ((size_t)b * TT + (size_t)qb * BM) * HD;
#pragma unroll
    for (int it = 0; it < 8; it++) {
        int f = tid + it * 256;
        int row = f >> 4, c4 = (f & 15) << 2;
        cp_async16(smem_u32(&Ps[row][c4]), &Qg[(size_t)row * HD + c4]);
    }
    cp_commit();
    kv_load(jb_lo, 0);
    cp_wait<1>();           // Q ready
    __syncthreads();

    uint32_t qf[8][4];
#pragma unroll
    for (int kk = 0; kk < 8; kk++) {
        uint2 uq0 = *(const uint2*)&Ps[16 * w + g][8 * kk + 2 * c];
        uint2 uq1 = *(const uint2*)&Ps[16 * w + g + 8][8 * kk + 2 * c];
        qf[kk][0] = uq0.x; qf[kk][2] = uq0.y;
        qf[kk][1] = uq1.x; qf[kk][3] = uq1.y;
    }

    float o[8][4];
#pragma unroll
    for (int nb = 0; nb < 8; nb++)
#pragma unroll
        for (int i = 0; i < 4; i++) o[nb][i] = 0.f;
    float m0 = -INFINITY, m1 = -INFINITY, l0 = 0.f, l1 = 0.f;

#pragma unroll 1
    for (int jb = jb_lo; jb < jb_hi; jb++) {
        const int bi = (jb - jb_lo) & 1;
        __syncthreads();
        if (jb + 1 < jb_hi) {
            kv_load(jb + 1, bi ^ 1);
            cp_wait<1>();
        } else {
            cp_wait<0>();
        }
        __syncthreads();

        const uint32_t (*Ks)[PAD] = (const uint32_t(*)[PAD])(smem + bi * KVBUF);
        const uint32_t (*Vs)[PAD] = (const uint32_t(*)[PAD])(smem + bi * KVBUF + 64 * PAD);

        // ---- S = Q K^T ----
        float s[8][4];
#pragma unroll
        for (int nb = 0; nb < 8; nb++) {
            s[nb][0] = s[nb][1] = s[nb][2] = s[nb][3] = 0.f;
#pragma unroll
            for (int kk = 0; kk < 8; kk++) {
                uint2 ub = *(const uint2*)&Ks[8 * nb + g][8 * kk + 2 * c];
                mma_tf32(s[nb][0], s[nb][1], s[nb][2], s[nb][3],
                         qf[kk][0], qf[kk][1], qf[kk][2], qf[kk][3], ub.x, ub.y);
            }
        }

        if (jb >= n_tiles - 2) {
            const int row0g = qb * BM + 16 * w + g;
            const int col0g = jb * BN + 2 * c;
#pragma unroll
            for (int nb = 0; nb < 8; nb++) {
                int cg = col0g + 8 * nb;
                if (cg     > row0g)     s[nb][0] = -INFINITY;
                if (cg + 1 > row0g)     s[nb][1] = -INFINITY;
                if (cg     > row0g + 8) s[nb][2] = -INFINITY;
                if (cg + 1 > row0g + 8) s[nb][3] = -INFINITY;
            }
        }

        // ---- online softmax (base-2); P kept in registers as tf32 bits ----
        float mx0 = -INFINITY, mx1 = -INFINITY;
#pragma unroll
        for (int nb = 0; nb < 8; nb++) {
            mx0 = fmaxf(mx0, fmaxf(s[nb][0], s[nb][1]));
            mx1 = fmaxf(mx1, fmaxf(s[nb][2], s[nb][3]));
        }
#pragma unroll
        for (int off = 1; off <= 2; off <<= 1) {
            mx0 = fmaxf(mx0, __shfl_xor_sync(0xffffffffu, mx0, off));
            mx1 = fmaxf(mx1, __shfl_xor_sync(0xffffffffu, mx1, off));
        }
        float mn0 = fmaxf(m0, mx0), mn1 = fmaxf(m1, mx1);
        float a0 = exp2f(m0 - mn0), a1 = exp2f(m1 - mn1);
        m0 = mn0; m1 = mn1;

        float rs0 = 0.f, rs1 = 0.f;
#pragma unroll
        for (int nb = 0; nb < 8; nb++) {
            float p0 = exp2f(s[nb][0] - m0);
            float p1 = exp2f(s[nb][1] - m0);
            float p2 = exp2f(s[nb][2] - m1);
            float p3 = exp2f(s[nb][3] - m1);
            rs0 += p0 + p1; rs1 += p2 + p3;
            s[nb][0] = __uint_as_float(f2tf(p0));
            s[nb][1] = __uint_as_float(f2tf(p1));
            s[nb][2] = __uint_as_float(f2tf(p2));
            s[nb][3] = __uint_as_float(f2tf(p3));
        }
#pragma unroll
        for (int off = 1; off <= 2; off <<= 1) {
            rs0 += __shfl_xor_sync(0xffffffffu, rs0, off);
            rs1 += __shfl_xor_sync(0xffffffffu, rs1, off);
        }
        l0 = l0 * a0 + rs0;
        l1 = l1 * a1 + rs1;
#pragma unroll
        for (int nb = 0; nb < 8; nb++) {
            o[nb][0] *= a0; o[nb][1] *= a0;
            o[nb][2] *= a1; o[nb][3] *= a1;
        }

        // ---- O += P V (P A-frags directly from registers) ----
#pragma unroll
        for (int kk = 0; kk < 8; kk++) {
            uint32_t pa0 = __float_as_uint(s[kk][0]);   // row g,   k-slot c   -> tok 8kk+2c
            uint32_t pa1 = __float_as_uint(s[kk][2]);   // row g+8, k-slot c
            uint32_t pa2 = __float_as_uint(s[kk][1]);   // row g,   k-slot c+4 -> tok 8kk+2c+1
            uint32_t pa3 = __float_as_uint(s[kk][3]);   // row g+8, k-slot c+4
#pragma unroll
            for (int nb = 0; nb < 8; nb++) {
                uint2 uv = *(const uint2*)&Vs[8 * nb + g][8 * kk + 2 * c];
                mma_tf32(o[nb][0], o[nb][1], o[nb][2], o[nb][3],
                         pa0, pa1, pa2, pa3, uv.x, uv.y);
            }
        }
    }

    const int p = ((b * QB_PER_B + qb) << 2) + sp;
    float* pacc = g_pacc + (size_t)p * BM * HD;
    const int r0 = 16 * w + g;
#pragma unroll
    for (int nb = 0; nb < 8; nb++) {
        *(float2*)&pacc[(size_t)r0 * HD + 8 * nb + 2 * c]       = make_float2(o[nb][0], o[nb][1]);
        *(float2*)&pacc[(size_t)(r0 + 8) * HD + 8 * nb + 2 * c] = make_float2(o[nb][2], o[nb][3]);
    }
    if (c == 0) {
        g_pm[p * BM + r0] = m0;     g_pm[p * BM + r0 + 8] = m1;
        g_pl[p * BM + r0] = l0;     g_pl[p * BM + r0 + 8] = l1;
    }
}

// ---------------------------------------------------------------------------
// Combine split partials -> output. Grid (128, 4): block = 32 rows x 64 cols,
// 2 float4 outputs per thread (2x MLP vs R10).
// ---------------------------------------------------------------------------
__global__ __launch_bounds__(256) void combine_kernel(float* __restrict__ out) {
    __shared__ float wsm[4][32];
    __shared__ float linv[32];

    const int bq = blockIdx.x;                 // 0..127
    const int b = bq >> 5;
    const int qb = bq & 31;
    const int nS = qb / 8 + 1;                 // 1..4 splits
    const int yc = blockIdx.y;                 // row chunk 0..3 (32 rows each)
    const int tid = threadIdx.x;
    const int pbase = bq << 2;

    if (tid < 32) {
        int row = yc * 32 + tid;
        float M = -INFINITY;
#pragma unroll 4
        for (int s = 0; s < nS; s++)
            M = fmaxf(M, g_pm[(pbase + s) * BM + row]);
        float L = 0.f;
#pragma unroll 4
        for (int s = 0; s < nS; s++) {
            float wgt = exp2f(g_pm[(pbase + s) * BM + row] - M);
            wsm[s][tid] = wgt;
            L += g_pl[(pbase + s) * BM + row] * wgt;
        }
        linv[tid] = 1.0f / L;
    }
    __syncthreads();

    float* og = out + ((size_t)b * TT + (size_t)qb * BM) * HD;

#pragma unroll
    for (int e = 0; e < 2; e++) {
        int f = tid + e * 256;                 // 0..511 float4 slots (32 rows x 16)
        int row_l = f >> 4;                    // 0..31
        int c4 = (f & 15) << 2;                // 0..60
        int row = yc * 32 + row_l;
        size_t off = (size_t)row * HD + c4;

        float4 sum = make_float4(0.f, 0.f, 0.f, 0.f);
#pragma unroll 4
        for (int s = 0; s < nS; s++) {
            float4 v = *(const float4*)&g_pacc[(size_t)(pbase + s) * BM * HD + off];
            float wgt = wsm[s][row_l];
            sum.x += v.x * wgt;
            sum.y += v.y * wgt;
            sum.z += v.z * wgt;
            sum.w += v.w * wgt;
        }
        float li = linv[row_l];
        sum.x *= li; sum.y *= li; sum.z *= li; sum.w *= li;
        *(float4*)&og[off] = sum;
    }
}

// ---------------------------------------------------------------------------
extern "C" void kernel_launch(void* const* d_in, const int* in_sizes, int n_in,
                              void* d_out, int out_size) {
    const float* x  = (const float*)d_in[0];
    const float* Wk = (const float*)d_in[1];
    const float* Wq = (const float*)d_in[2];
    const float* Wv = (const float*)d_in[3];
    float* out = (float*)d_out;
    (void)in_sizes; (void)n_in; (void)out_size;

    const int proj_smem = (2 * XRSZ + 4 * WSZ) * (int)sizeof(uint32_t);     // 139264
    const int flash_smem = (2 * KVBUF + 128 * PAD) * (int)sizeof(uint32_t); // 110592
    cudaFuncSetAttribute(proj_kernel,
                         cudaFuncAttributeMaxDynamicSharedMemorySize, proj_smem);
    cudaFuncSetAttribute(flash_kernel,
                         cudaFuncAttributeMaxDynamicSharedMemorySize, flash_smem);

    prep_kernel<<<96, 256>>>(Wk, Wq, Wv);
    proj_kernel<<<128, 512, proj_smem>>>(x);
    flash_kernel<<<NITEMS, 256, flash_smem>>>();
    combine_kernel<<<dim3(128, 4), 256>>>(out);
}